// round 1
// baseline (speedup 1.0000x reference)
#include <cuda_runtime.h>
#include <math.h>

// ---------------------------------------------------------------------------
// Problem constants
// ---------------------------------------------------------------------------
#define GN 16384                  // spatial N = H*W
#define ECH 256                   // embed channels (= C)
#define NB 8                      // total batches (twoB)
#define HB 4                      // half batch
#define NSPLIT 8                  // n-split for NT score GEMMs
static const size_t BSTR = (size_t)ECH * GN;      // per-batch plane: 4,194,304 floats
static const size_t TOT8 = (size_t)NB * BSTR;     // 33,554,432 floats
static const size_t TOT4 = (size_t)HB * BSTR;

// ---------------------------------------------------------------------------
// Scratch (device globals: allocation-free per harness rules)
// ---------------------------------------------------------------------------
__device__ float g_emb[33554432];                 // gelu(w_in @ x), all 8 batches
__device__ float g_nrm[33554432];                 // inorm(emb) ; later reused for inorm(pre)
__device__ float g_pre[33554432];                 // sa_u / ca_l (pre final norm)
__device__ float g_q[16777216];                   // Q (upper), later Ql (lower)
__device__ float g_k[16777216];                   // K (upper)
__device__ float g_v[16777216];                   // V (upper)
__device__ float g_t[16777216];                   // attn@V scratch
__device__ float g_pu[4 * NSPLIT * 256 * 256];    // upper score partials
__device__ float g_pl[4 * NSPLIT * 256 * 512];    // lower score partials
__device__ float g_su[4 * 256 * 256];             // upper softmax(attn)
__device__ float g_sl[4 * 256 * 512];             // lower softmax(attn)

// ---------------------------------------------------------------------------
// Helpers
// ---------------------------------------------------------------------------
__device__ __forceinline__ float gelu_exact(float x) {
    return 0.5f * x * (1.0f + erff(x * 0.70710678118654752f));
}

__device__ __forceinline__ float block_reduce_sum(float v, float* sbuf) {
    int tid = threadIdx.x;
    sbuf[tid] = v;
    __syncthreads();
    for (int s = 128; s > 0; s >>= 1) {
        if (tid < s) sbuf[tid] += sbuf[tid + s];
        __syncthreads();
    }
    float r = sbuf[0];
    __syncthreads();
    return r;
}

__device__ __forceinline__ float block_reduce_max(float v, float* sbuf) {
    int tid = threadIdx.x;
    sbuf[tid] = v;
    __syncthreads();
    for (int s = 128; s > 0; s >>= 1) {
        if (tid < s) sbuf[tid] = fmaxf(sbuf[tid], sbuf[tid + s]);
        __syncthreads();
    }
    float r = sbuf[0];
    __syncthreads();
    return r;
}

// ---------------------------------------------------------------------------
// Generic "conv1x1"-shape GEMM:  C[b](256 x 16384) = A (256 x K) @ B[b](K x 16384)
// A row-major [o][k] (weight or per-batch attn matrix), B row-major [k][n].
// epi: 0 = none, 1 = gelu, 2 = +R residual
// Tile: BM=64 (o), BN=128 (n), BK=16. 256 threads, 4x8 per-thread tile.
// ---------------------------------------------------------------------------
__global__ __launch_bounds__(256)
void gemm_kernel(const float* __restrict__ A, size_t aBs,
                 const float* __restrict__ Bm, size_t bBs,
                 float* __restrict__ C, size_t cBs,
                 const float* __restrict__ R, size_t rBs,
                 int K, int epi) {
    int b = blockIdx.z;
    A += (size_t)b * aBs;
    Bm += (size_t)b * bBs;
    C += (size_t)b * cBs;
    if (R) R += (size_t)b * rBs;

    __shared__ float As[16][64];     // [k][o]
    __shared__ float Bs[16][128];    // [k][n]

    int tid = threadIdx.x;
    int tx = tid & 15;               // n direction (8 per thread)
    int ty = tid >> 4;               // o direction (4 per thread)
    int oBase = blockIdx.y * 64;
    int nBase = blockIdx.x * 128;

    // load mapping
    int ar = tid >> 2;               // 0..63 (o row in tile)
    int ac = (tid & 3) * 4;          // k offset (float4)
    int br = tid >> 4;               // 0..15 (k row)
    int bc = (tid & 15) * 8;         // n offset (2x float4)

    float acc[4][8];
#pragma unroll
    for (int i = 0; i < 4; i++)
#pragma unroll
        for (int j = 0; j < 8; j++) acc[i][j] = 0.0f;

    for (int kk = 0; kk < K; kk += 16) {
        float4 av = *(const float4*)&A[(size_t)(oBase + ar) * K + kk + ac];
        As[ac + 0][ar] = av.x;
        As[ac + 1][ar] = av.y;
        As[ac + 2][ar] = av.z;
        As[ac + 3][ar] = av.w;
        const float* bp = &Bm[(size_t)(kk + br) * GN + nBase + bc];
        *(float4*)&Bs[br][bc] = *(const float4*)bp;
        *(float4*)&Bs[br][bc + 4] = *(const float4*)(bp + 4);
        __syncthreads();

#pragma unroll
        for (int k = 0; k < 16; k++) {
            float4 a4 = *(float4*)&As[k][ty * 4];
            float4 b0 = *(float4*)&Bs[k][tx * 8];
            float4 b1 = *(float4*)&Bs[k][tx * 8 + 4];
            float av4[4] = {a4.x, a4.y, a4.z, a4.w};
            float bv[8] = {b0.x, b0.y, b0.z, b0.w, b1.x, b1.y, b1.z, b1.w};
#pragma unroll
            for (int i = 0; i < 4; i++)
#pragma unroll
                for (int j = 0; j < 8; j++) acc[i][j] = fmaf(av4[i], bv[j], acc[i][j]);
        }
        __syncthreads();
    }

#pragma unroll
    for (int i = 0; i < 4; i++) {
        int orow = oBase + ty * 4 + i;
        size_t base = (size_t)orow * GN + nBase + tx * 8;
        float o[8];
#pragma unroll
        for (int j = 0; j < 8; j++) o[j] = acc[i][j];
        if (epi == 2) {
            float4 r0 = *(const float4*)&R[base];
            float4 r1 = *(const float4*)&R[base + 4];
            o[0] += r0.x; o[1] += r0.y; o[2] += r0.z; o[3] += r0.w;
            o[4] += r1.x; o[5] += r1.y; o[6] += r1.z; o[7] += r1.w;
        } else if (epi == 1) {
#pragma unroll
            for (int j = 0; j < 8; j++) o[j] = gelu_exact(o[j]);
        }
        *(float4*)&C[base] = make_float4(o[0], o[1], o[2], o[3]);
        *(float4*)&C[base + 4] = make_float4(o[4], o[5], o[6], o[7]);
    }
}

// ---------------------------------------------------------------------------
// NT score GEMM: P[b][s][i][j] = sum_{n in chunk s} Q[b][i][n] * K[b][j][n]
// (scale applied later, during the reduce in inorm_softmax)
// I = 256 fixed. grid: (J/64, I/64, HB*NSPLIT). 64x64 tile, 4x4 per thread.
// ---------------------------------------------------------------------------
__global__ __launch_bounds__(256)
void gemmnt_kernel(const float* __restrict__ Q, size_t qBs,
                   const float* __restrict__ Km, size_t kBs,
                   float* __restrict__ P, int J) {
    int z = blockIdx.z;
    int b = z / NSPLIT;
    int s = z % NSPLIT;
    Q += (size_t)b * qBs;
    Km += (size_t)b * kBs;

    __shared__ float Qs[16][64];     // [n][i]
    __shared__ float Ks[16][64];     // [n][j]

    int tid = threadIdx.x;
    int tx = tid & 15;               // j direction (4 per thread)
    int ty = tid >> 4;               // i direction (4 per thread)
    int iBase = blockIdx.y * 64;
    int jBase = blockIdx.x * 64;

    int r = tid >> 2;                // 0..63 (row of tile)
    int c = (tid & 3) * 4;           // n offset (float4)

    float acc[4][4];
#pragma unroll
    for (int i = 0; i < 4; i++)
#pragma unroll
        for (int j = 0; j < 4; j++) acc[i][j] = 0.0f;

    const int chunk = GN / NSPLIT;   // 2048
    int n0 = s * chunk;
    int n1 = n0 + chunk;

    for (int nn = n0; nn < n1; nn += 16) {
        float4 qv = *(const float4*)&Q[(size_t)(iBase + r) * GN + nn + c];
        Qs[c + 0][r] = qv.x; Qs[c + 1][r] = qv.y; Qs[c + 2][r] = qv.z; Qs[c + 3][r] = qv.w;
        float4 kv4 = *(const float4*)&Km[(size_t)(jBase + r) * GN + nn + c];
        Ks[c + 0][r] = kv4.x; Ks[c + 1][r] = kv4.y; Ks[c + 2][r] = kv4.z; Ks[c + 3][r] = kv4.w;
        __syncthreads();

#pragma unroll
        for (int k = 0; k < 16; k++) {
            float4 qi = *(float4*)&Qs[k][ty * 4];
            float4 kj = *(float4*)&Ks[k][tx * 4];
            float qa[4] = {qi.x, qi.y, qi.z, qi.w};
            float kb[4] = {kj.x, kj.y, kj.z, kj.w};
#pragma unroll
            for (int i = 0; i < 4; i++)
#pragma unroll
                for (int j = 0; j < 4; j++) acc[i][j] = fmaf(qa[i], kb[j], acc[i][j]);
        }
        __syncthreads();
    }

#pragma unroll
    for (int i = 0; i < 4; i++) {
        size_t base = (((size_t)(b * NSPLIT + s) * 256) + iBase + ty * 4 + i) * J + jBase + tx * 4;
        *(float4*)&P[base] = make_float4(acc[i][0], acc[i][1], acc[i][2], acc[i][3]);
    }
}

// ---------------------------------------------------------------------------
// Instance-norm over long rows (length GN), optional gamma/beta per channel.
// One block (256 thr) per row. grid = NB*ECH.
// ---------------------------------------------------------------------------
__global__ __launch_bounds__(256)
void inorm_rows(const float* __restrict__ X, float* __restrict__ Y,
                const float* __restrict__ gamma, const float* __restrict__ beta) {
    __shared__ float sbuf[256];
    int row = blockIdx.x;
    int c = row & (ECH - 1);
    const float4* xr = (const float4*)(X + (size_t)row * GN);
    float4* yr = (float4*)(Y + (size_t)row * GN);

    float s = 0.0f, ss = 0.0f;
    for (int idx = threadIdx.x; idx < GN / 4; idx += 256) {
        float4 v = xr[idx];
        s += v.x + v.y + v.z + v.w;
        ss += v.x * v.x + v.y * v.y + v.z * v.z + v.w * v.w;
    }
    float tot = block_reduce_sum(s, sbuf);
    float tot2 = block_reduce_sum(ss, sbuf);
    const float inv = 1.0f / (float)GN;
    float mu = tot * inv;
    float var = tot2 * inv - mu * mu;
    float rstd = rsqrtf(var + 1e-5f);
    float g = gamma ? gamma[c] : 1.0f;
    float be = beta ? beta[c] : 0.0f;
    float a = rstd * g;
    float bb = be - mu * a;

    for (int idx = threadIdx.x; idx < GN / 4; idx += 256) {
        float4 v = xr[idx];
        v.x = v.x * a + bb;
        v.y = v.y * a + bb;
        v.z = v.z * a + bb;
        v.w = v.w * a + bb;
        yr[idx] = v;
    }
}

// ---------------------------------------------------------------------------
// Reduce NSPLIT partials -> scale -> instance-norm (no affine) -> softmax.
// One block per (b, i) row; J = 256 or 512. grid = HB*256.
// ---------------------------------------------------------------------------
__global__ __launch_bounds__(256)
void inorm_softmax(const float* __restrict__ P, float* __restrict__ S,
                   int J, float scale) {
    __shared__ float rowbuf[512];
    __shared__ float sbuf[256];
    int row = blockIdx.x;
    int b = row >> 8;
    int i = row & 255;
    int tid = threadIdx.x;

    for (int j = tid; j < J; j += 256) {
        float v = 0.0f;
#pragma unroll
        for (int s = 0; s < NSPLIT; s++)
            v += P[(((size_t)(b * NSPLIT + s) * 256) + i) * J + j];
        rowbuf[j] = v * scale;
    }
    __syncthreads();

    float ls = 0.0f;
    for (int j = tid; j < J; j += 256) ls += rowbuf[j];
    float mean = block_reduce_sum(ls, sbuf) / (float)J;

    float lv = 0.0f;
    for (int j = tid; j < J; j += 256) {
        float d = rowbuf[j] - mean;
        lv += d * d;
    }
    float var = block_reduce_sum(lv, sbuf) / (float)J;
    float rstd = rsqrtf(var + 1e-5f);

    float lm = -1e30f;
    for (int j = tid; j < J; j += 256) {
        float t = (rowbuf[j] - mean) * rstd;
        rowbuf[j] = t;
        lm = fmaxf(lm, t);
    }
    float mx = block_reduce_max(lm, sbuf);

    float le = 0.0f;
    for (int j = tid; j < J; j += 256) {
        float e = expf(rowbuf[j] - mx);
        rowbuf[j] = e;
        le += e;
    }
    float denom = block_reduce_sum(le, sbuf);
    float rden = 1.0f / denom;

    for (int j = tid; j < J; j += 256)
        S[((size_t)b * 256 + i) * J + j] = rowbuf[j] * rden;
}

// ---------------------------------------------------------------------------
// Launch
// ---------------------------------------------------------------------------
extern "C" void kernel_launch(void* const* d_in, const int* in_sizes, int n_in,
                              void* d_out, int out_size) {
    const float* feat  = (const float*)d_in[0];
    const float* kv    = (const float*)d_in[1];
    const float* w_in  = (const float*)d_in[2];
    const float* w_out = (const float*)d_in[3];
    const float* wq_sa = (const float*)d_in[4];
    const float* wk_sa = (const float*)d_in[5];
    const float* wv_sa = (const float*)d_in[6];
    const float* wo_sa = (const float*)d_in[7];
    const float* wq_ca = (const float*)d_in[8];
    const float* wo_ca = (const float*)d_in[9];
    const float* ag    = (const float*)d_in[10];
    const float* ab    = (const float*)d_in[11];
    const float* eg    = (const float*)d_in[12];
    const float* eb    = (const float*)d_in[13];
    float* out = (float*)d_out;

    float *emb, *nrm, *pre, *q, *k, *v, *t, *pu, *pl, *su, *sl;
    cudaGetSymbolAddress((void**)&emb, g_emb);
    cudaGetSymbolAddress((void**)&nrm, g_nrm);
    cudaGetSymbolAddress((void**)&pre, g_pre);
    cudaGetSymbolAddress((void**)&q,   g_q);
    cudaGetSymbolAddress((void**)&k,   g_k);
    cudaGetSymbolAddress((void**)&v,   g_v);
    cudaGetSymbolAddress((void**)&t,   g_t);
    cudaGetSymbolAddress((void**)&pu,  g_pu);
    cudaGetSymbolAddress((void**)&pl,  g_pl);
    cudaGetSymbolAddress((void**)&su,  g_su);
    cudaGetSymbolAddress((void**)&sl,  g_sl);

    const float scale = 1.0f / 128.0f;   // N^{-1/2}, N = 16384
    dim3 blk(256);
    dim3 g8(GN / 128, 4, 8);
    dim3 g4(GN / 128, 4, 4);

    // 1. emb = gelu(w_in @ x), all 8 batches
    gemm_kernel<<<g8, blk>>>(w_in, 0, feat, BSTR, emb, BSTR, nullptr, 0, 256, 1);
    // 2. nrm = inorm(emb, attn_gamma, attn_beta)
    inorm_rows<<<NB * ECH, blk>>>(emb, nrm, ag, ab);
    // 3-5. upper Q/K/V = w{q,k,v}_sa @ nrm_u
    gemm_kernel<<<g4, blk>>>(wq_sa, 0, nrm + TOT4, BSTR, q, BSTR, nullptr, 0, 256, 0);
    gemm_kernel<<<g4, blk>>>(wk_sa, 0, nrm + TOT4, BSTR, k, BSTR, nullptr, 0, 256, 0);
    gemm_kernel<<<g4, blk>>>(wv_sa, 0, nrm + TOT4, BSTR, v, BSTR, nullptr, 0, 256, 0);
    // 6. upper score partials: Q . K^T over n
    gemmnt_kernel<<<dim3(4, 4, HB * NSPLIT), blk>>>(q, BSTR, k, BSTR, pu, 256);
    // 7. reduce + scale + inorm + softmax
    inorm_softmax<<<HB * 256, blk>>>(pu, su, 256, scale);
    // 8. attn @ V
    gemm_kernel<<<g4, blk>>>(su, 256 * 256, v, BSTR, t, BSTR, nullptr, 0, 256, 0);
    // 9. sa_u = wo_sa @ (attn@V) + emb_u   -> pre[4..7]
    gemm_kernel<<<g4, blk>>>(wo_sa, 0, t, BSTR, pre + TOT4, BSTR, emb + TOT4, BSTR, 256, 2);
    // 10. lower Ql = wq_ca @ nrm_l  (reuse q)
    gemm_kernel<<<g4, blk>>>(wq_ca, 0, nrm, BSTR, q, BSTR, nullptr, 0, 256, 0);
    // 11. lower score partials: Ql . kv^T  (kv shared across batches)
    gemmnt_kernel<<<dim3(8, 4, HB * NSPLIT), blk>>>(q, BSTR, kv, 0, pl, 512);
    // 12. reduce + scale + inorm + softmax (J = 512)
    inorm_softmax<<<HB * 256, blk>>>(pl, sl, 512, scale);
    // 13. ca = attn_l @ kv   (K = 512)
    gemm_kernel<<<g4, blk>>>(sl, 256 * 512, kv, 0, t, BSTR, nullptr, 0, 512, 0);
    // 14. ca_l = wo_ca @ ca + emb_l   -> pre[0..3]
    gemm_kernel<<<g4, blk>>>(wo_ca, 0, t, BSTR, pre, BSTR, emb, BSTR, 256, 2);
    // 15. nrm = inorm(pre, enc_gamma, enc_beta) (reuse nrm buffer)
    inorm_rows<<<NB * ECH, blk>>>(pre, nrm, eg, eb);
    // 16. out = gelu(w_out @ nrm), all 8 batches, straight to d_out
    gemm_kernel<<<g8, blk>>>(w_out, 0, nrm, BSTR, out, BSTR, nullptr, 0, 256, 1);
}

// round 2
// speedup vs baseline: 1.8901x; 1.8901x over previous
#include <cuda_runtime.h>
#include <math.h>

// ---------------------------------------------------------------------------
// Problem constants
// ---------------------------------------------------------------------------
#define GN 16384                  // spatial N = H*W
#define ECH 256                   // embed channels (= C)
#define NB 8                      // total batches (twoB)
#define HB 4                      // half batch
#define NSPLIT 16                 // n-split for NT score GEMMs
static const size_t BSTR = (size_t)ECH * GN;      // per-batch plane
static const size_t TOT4 = (size_t)HB * BSTR;

// ---------------------------------------------------------------------------
// Scratch (device globals: allocation-free per harness rules)
// ---------------------------------------------------------------------------
__device__ float g_emb[33554432];
__device__ float g_nrm[33554432];
__device__ float g_pre[33554432];
__device__ float g_q[16777216];
__device__ float g_k[16777216];
__device__ float g_v[16777216];
__device__ float g_t[16777216];
__device__ float g_pu[HB * NSPLIT * 256 * 256];
__device__ float g_pl[HB * NSPLIT * 256 * 512];
__device__ float g_su[HB * 256 * 256];
__device__ float g_sl[HB * 256 * 512];

typedef unsigned long long ull;

// ---------------------------------------------------------------------------
// Packed f32x2 helpers (sm_103a FFMA2 path)
// ---------------------------------------------------------------------------
__device__ __forceinline__ ull pk2(float lo, float hi) {
    ull r; asm("mov.b64 %0, {%1, %2};" : "=l"(r) : "f"(lo), "f"(hi)); return r;
}
__device__ __forceinline__ ull dup2(float x) {
    ull r; asm("mov.b64 %0, {%1, %1};" : "=l"(r) : "f"(x)); return r;
}
__device__ __forceinline__ void upk2(ull v, float& lo, float& hi) {
    asm("mov.b64 {%0, %1}, %2;" : "=f"(lo), "=f"(hi) : "l"(v));
}
__device__ __forceinline__ ull ffma2(ull a, ull b, ull c) {
    ull d; asm("fma.rn.f32x2 %0, %1, %2, %3;" : "=l"(d) : "l"(a), "l"(b), "l"(c)); return d;
}

__device__ __forceinline__ float gelu_exact(float x) {
    return 0.5f * x * (1.0f + erff(x * 0.70710678118654752f));
}

__device__ __forceinline__ float block_reduce_sum(float v, float* sbuf) {
    int tid = threadIdx.x;
    sbuf[tid] = v;
    __syncthreads();
    for (int s = 128; s > 0; s >>= 1) {
        if (tid < s) sbuf[tid] += sbuf[tid + s];
        __syncthreads();
    }
    float r = sbuf[0];
    __syncthreads();
    return r;
}

__device__ __forceinline__ float block_reduce_max(float v, float* sbuf) {
    int tid = threadIdx.x;
    sbuf[tid] = v;
    __syncthreads();
    for (int s = 128; s > 0; s >>= 1) {
        if (tid < s) sbuf[tid] = fmaxf(sbuf[tid], sbuf[tid + s]);
        __syncthreads();
    }
    float r = sbuf[0];
    __syncthreads();
    return r;
}

// ---------------------------------------------------------------------------
// conv1x1 GEMM: C[b](256 x 16384) = A(256 x K) @ B[b](K x 16384)
// 128x128x16 tile, 256 threads, 8x8 per-thread register tile, FFMA2 inner.
// epi: 0 none, 1 gelu, 2 +R residual
// ---------------------------------------------------------------------------
__global__ __launch_bounds__(256, 2)
void gemm128(const float* __restrict__ A, size_t aBs,
             const float* __restrict__ Bm, size_t bBs,
             float* __restrict__ C, size_t cBs,
             const float* __restrict__ R, size_t rBs,
             int K, int epi) {
    int b = blockIdx.z;
    A += (size_t)b * aBs;
    Bm += (size_t)b * bBs;
    C += (size_t)b * cBs;
    if (R) R += (size_t)b * rBs;

    __shared__ float As[16][128];   // [k][o]
    __shared__ float Bs[16][128];   // [k][n]

    int tid = threadIdx.x;
    int tx = tid & 15;              // n: 4+4 cols at tx*4 and 64+tx*4
    int ty = tid >> 4;              // o: 8 rows at ty*8
    int oBase = blockIdx.y * 128;
    int nBase = blockIdx.x * 128;

    int ar = tid >> 1, ac = (tid & 1) * 8;      // A tile load: row ar, k-offset ac
    int br = tid >> 4, bc = (tid & 15) * 4;     // B tile load: k-row br, col bc (+64)

    const float* Ap = A + (size_t)(oBase + ar) * K + ac;
    const float* Bp = Bm + (size_t)br * GN + nBase + bc;

    ull acc[8][4];
#pragma unroll
    for (int i = 0; i < 8; i++)
#pragma unroll
        for (int j = 0; j < 4; j++) acc[i][j] = 0ull;

    float4 pa0 = *(const float4*)Ap;
    float4 pa1 = *(const float4*)(Ap + 4);
    float4 pb0 = *(const float4*)Bp;
    float4 pb1 = *(const float4*)(Bp + 64);

    int KT = K >> 4;
    for (int t = 0; t < KT; t++) {
        As[ac + 0][ar] = pa0.x; As[ac + 1][ar] = pa0.y;
        As[ac + 2][ar] = pa0.z; As[ac + 3][ar] = pa0.w;
        As[ac + 4][ar] = pa1.x; As[ac + 5][ar] = pa1.y;
        As[ac + 6][ar] = pa1.z; As[ac + 7][ar] = pa1.w;
        *(float4*)&Bs[br][bc] = pb0;
        *(float4*)&Bs[br][64 + bc] = pb1;
        __syncthreads();

        if (t + 1 < KT) {
            const float* An = Ap + (t + 1) * 16;
            const float* Bn = Bp + (size_t)(t + 1) * 16 * GN;
            pa0 = *(const float4*)An;
            pa1 = *(const float4*)(An + 4);
            pb0 = *(const float4*)Bn;
            pb1 = *(const float4*)(Bn + 64);
        }

#pragma unroll
        for (int k = 0; k < 16; k++) {
            float4 a0 = *(float4*)&As[k][ty * 8];
            float4 a1 = *(float4*)&As[k][ty * 8 + 4];
            float4 b0 = *(float4*)&Bs[k][tx * 4];
            float4 b1 = *(float4*)&Bs[k][64 + tx * 4];
            ull bp[4] = { pk2(b0.x, b0.y), pk2(b0.z, b0.w),
                          pk2(b1.x, b1.y), pk2(b1.z, b1.w) };
            float av[8] = { a0.x, a0.y, a0.z, a0.w, a1.x, a1.y, a1.z, a1.w };
#pragma unroll
            for (int i = 0; i < 8; i++) {
                ull ad = dup2(av[i]);
#pragma unroll
                for (int j = 0; j < 4; j++) acc[i][j] = ffma2(ad, bp[j], acc[i][j]);
            }
        }
        __syncthreads();
    }

#pragma unroll
    for (int i = 0; i < 8; i++) {
        int orow = oBase + ty * 8 + i;
        size_t base = (size_t)orow * GN + nBase + tx * 4;
        float o[8];
        upk2(acc[i][0], o[0], o[1]); upk2(acc[i][1], o[2], o[3]);
        upk2(acc[i][2], o[4], o[5]); upk2(acc[i][3], o[6], o[7]);
        if (epi == 2) {
            float4 r0 = *(const float4*)&R[base];
            float4 r1 = *(const float4*)&R[base + 64];
            o[0] += r0.x; o[1] += r0.y; o[2] += r0.z; o[3] += r0.w;
            o[4] += r1.x; o[5] += r1.y; o[6] += r1.z; o[7] += r1.w;
        } else if (epi == 1) {
#pragma unroll
            for (int j = 0; j < 8; j++) o[j] = gelu_exact(o[j]);
        }
        *(float4*)&C[base] = make_float4(o[0], o[1], o[2], o[3]);
        *(float4*)&C[base + 64] = make_float4(o[4], o[5], o[6], o[7]);
    }
}

// ---------------------------------------------------------------------------
// NT score GEMM: P[b][s][i][j] = sum_{n in chunk s} Q[b][i][n] * K[b][j][n]
// 128x128 tile over (i,j), 16-wide n-steps, FFMA2 inner. Scale applied later.
// grid: (J/128, 256/128, HB*NSPLIT)
// ---------------------------------------------------------------------------
__global__ __launch_bounds__(256, 2)
void gemmnt128(const float* __restrict__ Q, size_t qBs,
               const float* __restrict__ Km, size_t kBs,
               float* __restrict__ P, int J) {
    int z = blockIdx.z;
    int b = z / NSPLIT;
    int s = z % NSPLIT;
    Q += (size_t)b * qBs;
    Km += (size_t)b * kBs;

    __shared__ float Qs[16][128];   // [n][i]
    __shared__ float Ks[16][128];   // [n][j]

    int tid = threadIdx.x;
    int tx = tid & 15;
    int ty = tid >> 4;
    int iBase = blockIdx.y * 128;
    int jBase = blockIdx.x * 128;

    int r = tid >> 1, c = (tid & 1) * 8;
    const int chunk = GN / NSPLIT;      // 1024
    int n0 = s * chunk;

    const float* Qp = Q + (size_t)(iBase + r) * GN + n0 + c;
    const float* Kp = Km + (size_t)(jBase + r) * GN + n0 + c;

    ull acc[8][4];
#pragma unroll
    for (int i = 0; i < 8; i++)
#pragma unroll
        for (int j = 0; j < 4; j++) acc[i][j] = 0ull;

    float4 pq0 = *(const float4*)Qp;
    float4 pq1 = *(const float4*)(Qp + 4);
    float4 pk0 = *(const float4*)Kp;
    float4 pk1 = *(const float4*)(Kp + 4);

    int KT = chunk >> 4;
    for (int t = 0; t < KT; t++) {
        Qs[c + 0][r] = pq0.x; Qs[c + 1][r] = pq0.y;
        Qs[c + 2][r] = pq0.z; Qs[c + 3][r] = pq0.w;
        Qs[c + 4][r] = pq1.x; Qs[c + 5][r] = pq1.y;
        Qs[c + 6][r] = pq1.z; Qs[c + 7][r] = pq1.w;
        Ks[c + 0][r] = pk0.x; Ks[c + 1][r] = pk0.y;
        Ks[c + 2][r] = pk0.z; Ks[c + 3][r] = pk0.w;
        Ks[c + 4][r] = pk1.x; Ks[c + 5][r] = pk1.y;
        Ks[c + 6][r] = pk1.z; Ks[c + 7][r] = pk1.w;
        __syncthreads();

        if (t + 1 < KT) {
            const float* Qn = Qp + (t + 1) * 16;
            const float* Kn = Kp + (t + 1) * 16;
            pq0 = *(const float4*)Qn; pq1 = *(const float4*)(Qn + 4);
            pk0 = *(const float4*)Kn; pk1 = *(const float4*)(Kn + 4);
        }

#pragma unroll
        for (int k = 0; k < 16; k++) {
            float4 a0 = *(float4*)&Qs[k][ty * 8];
            float4 a1 = *(float4*)&Qs[k][ty * 8 + 4];
            float4 b0 = *(float4*)&Ks[k][tx * 4];
            float4 b1 = *(float4*)&Ks[k][64 + tx * 4];
            ull bp[4] = { pk2(b0.x, b0.y), pk2(b0.z, b0.w),
                          pk2(b1.x, b1.y), pk2(b1.z, b1.w) };
            float av[8] = { a0.x, a0.y, a0.z, a0.w, a1.x, a1.y, a1.z, a1.w };
#pragma unroll
            for (int i = 0; i < 8; i++) {
                ull ad = dup2(av[i]);
#pragma unroll
                for (int j = 0; j < 4; j++) acc[i][j] = ffma2(ad, bp[j], acc[i][j]);
            }
        }
        __syncthreads();
    }

#pragma unroll
    for (int i = 0; i < 8; i++) {
        size_t base = (((size_t)(b * NSPLIT + s) * 256) + iBase + ty * 8 + i) * J
                      + jBase + tx * 4;
        float o[8];
        upk2(acc[i][0], o[0], o[1]); upk2(acc[i][1], o[2], o[3]);
        upk2(acc[i][2], o[4], o[5]); upk2(acc[i][3], o[6], o[7]);
        *(float4*)&P[base] = make_float4(o[0], o[1], o[2], o[3]);
        *(float4*)&P[base + 64] = make_float4(o[4], o[5], o[6], o[7]);
    }
}

// ---------------------------------------------------------------------------
// Instance-norm over rows of length GN with optional per-channel affine.
// ---------------------------------------------------------------------------
__global__ __launch_bounds__(256)
void inorm_rows(const float* __restrict__ X, float* __restrict__ Y,
                const float* __restrict__ gamma, const float* __restrict__ beta) {
    __shared__ float sbuf[256];
    int row = blockIdx.x;
    int cch = row & (ECH - 1);
    const float4* xr = (const float4*)(X + (size_t)row * GN);
    float4* yr = (float4*)(Y + (size_t)row * GN);

    float s = 0.0f, ss = 0.0f;
    for (int idx = threadIdx.x; idx < GN / 4; idx += 256) {
        float4 v = xr[idx];
        s += v.x + v.y + v.z + v.w;
        ss += v.x * v.x + v.y * v.y + v.z * v.z + v.w * v.w;
    }
    float tot = block_reduce_sum(s, sbuf);
    float tot2 = block_reduce_sum(ss, sbuf);
    const float inv = 1.0f / (float)GN;
    float mu = tot * inv;
    float var = tot2 * inv - mu * mu;
    float rstd = rsqrtf(var + 1e-5f);
    float g = gamma ? gamma[cch] : 1.0f;
    float be = beta ? beta[cch] : 0.0f;
    float a = rstd * g;
    float bb = be - mu * a;

    for (int idx = threadIdx.x; idx < GN / 4; idx += 256) {
        float4 v = xr[idx];
        v.x = v.x * a + bb; v.y = v.y * a + bb;
        v.z = v.z * a + bb; v.w = v.w * a + bb;
        yr[idx] = v;
    }
}

// ---------------------------------------------------------------------------
// Reduce NSPLIT partials -> scale -> inorm (no affine) -> softmax.
// ---------------------------------------------------------------------------
__global__ __launch_bounds__(256)
void inorm_softmax(const float* __restrict__ P, float* __restrict__ S,
                   int J, float scale) {
    __shared__ float rowbuf[512];
    __shared__ float sbuf[256];
    int row = blockIdx.x;
    int b = row >> 8;
    int i = row & 255;
    int tid = threadIdx.x;

    for (int j = tid; j < J; j += 256) {
        float v = 0.0f;
#pragma unroll
        for (int s = 0; s < NSPLIT; s++)
            v += P[(((size_t)(b * NSPLIT + s) * 256) + i) * J + j];
        rowbuf[j] = v * scale;
    }
    __syncthreads();

    float ls = 0.0f;
    for (int j = tid; j < J; j += 256) ls += rowbuf[j];
    float mean = block_reduce_sum(ls, sbuf) / (float)J;

    float lv = 0.0f;
    for (int j = tid; j < J; j += 256) {
        float d = rowbuf[j] - mean;
        lv += d * d;
    }
    float var = block_reduce_sum(lv, sbuf) / (float)J;
    float rstd = rsqrtf(var + 1e-5f);

    float lm = -1e30f;
    for (int j = tid; j < J; j += 256) {
        float tt = (rowbuf[j] - mean) * rstd;
        rowbuf[j] = tt;
        lm = fmaxf(lm, tt);
    }
    float mx = block_reduce_max(lm, sbuf);

    float le = 0.0f;
    for (int j = tid; j < J; j += 256) {
        float e = expf(rowbuf[j] - mx);
        rowbuf[j] = e;
        le += e;
    }
    float denom = block_reduce_sum(le, sbuf);
    float rden = 1.0f / denom;

    for (int j = tid; j < J; j += 256)
        S[((size_t)b * 256 + i) * J + j] = rowbuf[j] * rden;
}

// ---------------------------------------------------------------------------
// Launch
// ---------------------------------------------------------------------------
extern "C" void kernel_launch(void* const* d_in, const int* in_sizes, int n_in,
                              void* d_out, int out_size) {
    const float* feat  = (const float*)d_in[0];
    const float* kv    = (const float*)d_in[1];
    const float* w_in  = (const float*)d_in[2];
    const float* w_out = (const float*)d_in[3];
    const float* wq_sa = (const float*)d_in[4];
    const float* wk_sa = (const float*)d_in[5];
    const float* wv_sa = (const float*)d_in[6];
    const float* wo_sa = (const float*)d_in[7];
    const float* wq_ca = (const float*)d_in[8];
    const float* wo_ca = (const float*)d_in[9];
    const float* ag    = (const float*)d_in[10];
    const float* ab    = (const float*)d_in[11];
    const float* eg    = (const float*)d_in[12];
    const float* eb    = (const float*)d_in[13];
    float* out = (float*)d_out;

    float *emb, *nrm, *pre, *q, *k, *v, *t, *pu, *pl, *su, *sl;
    cudaGetSymbolAddress((void**)&emb, g_emb);
    cudaGetSymbolAddress((void**)&nrm, g_nrm);
    cudaGetSymbolAddress((void**)&pre, g_pre);
    cudaGetSymbolAddress((void**)&q,   g_q);
    cudaGetSymbolAddress((void**)&k,   g_k);
    cudaGetSymbolAddress((void**)&v,   g_v);
    cudaGetSymbolAddress((void**)&t,   g_t);
    cudaGetSymbolAddress((void**)&pu,  g_pu);
    cudaGetSymbolAddress((void**)&pl,  g_pl);
    cudaGetSymbolAddress((void**)&su,  g_su);
    cudaGetSymbolAddress((void**)&sl,  g_sl);

    const float scale = 1.0f / 128.0f;   // N^{-1/2}
    dim3 blk(256);
    dim3 g8(GN / 128, 2, 8);
    dim3 g4(GN / 128, 2, 4);

    // 1. emb = gelu(w_in @ x)
    gemm128<<<g8, blk>>>(w_in, 0, feat, BSTR, emb, BSTR, nullptr, 0, 256, 1);
    // 2. nrm = inorm(emb, attn_gamma, attn_beta)
    inorm_rows<<<NB * ECH, blk>>>(emb, nrm, ag, ab);
    // 3-5. upper Q/K/V
    gemm128<<<g4, blk>>>(wq_sa, 0, nrm + TOT4, BSTR, q, BSTR, nullptr, 0, 256, 0);
    gemm128<<<g4, blk>>>(wk_sa, 0, nrm + TOT4, BSTR, k, BSTR, nullptr, 0, 256, 0);
    gemm128<<<g4, blk>>>(wv_sa, 0, nrm + TOT4, BSTR, v, BSTR, nullptr, 0, 256, 0);
    // 6. upper score partials
    gemmnt128<<<dim3(2, 2, HB * NSPLIT), blk>>>(q, BSTR, k, BSTR, pu, 256);
    // 7. reduce + inorm + softmax
    inorm_softmax<<<HB * 256, blk>>>(pu, su, 256, scale);
    // 8. attn @ V
    gemm128<<<g4, blk>>>(su, 256 * 256, v, BSTR, t, BSTR, nullptr, 0, 256, 0);
    // 9. sa_u = wo_sa @ t + emb_u
    gemm128<<<g4, blk>>>(wo_sa, 0, t, BSTR, pre + TOT4, BSTR, emb + TOT4, BSTR, 256, 2);
    // 10. lower Ql
    gemm128<<<g4, blk>>>(wq_ca, 0, nrm, BSTR, q, BSTR, nullptr, 0, 256, 0);
    // 11. lower score partials (kv shared across batches)
    gemmnt128<<<dim3(4, 2, HB * NSPLIT), blk>>>(q, BSTR, kv, 0, pl, 512);
    // 12. reduce + inorm + softmax (J=512)
    inorm_softmax<<<HB * 256, blk>>>(pl, sl, 512, scale);
    // 13. ca = attn_l @ kv (K=512)
    gemm128<<<g4, blk>>>(sl, 256 * 512, kv, 0, t, BSTR, nullptr, 0, 512, 0);
    // 14. ca_l = wo_ca @ ca + emb_l
    gemm128<<<g4, blk>>>(wo_ca, 0, t, BSTR, pre, BSTR, emb, BSTR, 256, 2);
    // 15. nrm = inorm(pre, enc_gamma, enc_beta)
    inorm_rows<<<NB * ECH, blk>>>(pre, nrm, eg, eb);
    // 16. out = gelu(w_out @ nrm)
    gemm128<<<g8, blk>>>(w_out, 0, nrm, BSTR, out, BSTR, nullptr, 0, 256, 1);
}

// round 3
// speedup vs baseline: 2.7700x; 1.4655x over previous
#include <cuda_runtime.h>
#include <cuda_bf16.h>
#include <math.h>

// ---------------------------------------------------------------------------
// Problem constants
// ---------------------------------------------------------------------------
#define GN 16384                  // spatial N = H*W
#define ECH 256                   // embed channels (= C)
#define NB 8                      // total batches (twoB)
#define HB 4                      // half batch
#define NSPLIT 16                 // n-split for NT score GEMMs
static const size_t BSTR = (size_t)ECH * GN;
static const size_t TOT4 = (size_t)HB * BSTR;

// ---------------------------------------------------------------------------
// Scratch
// ---------------------------------------------------------------------------
__device__ float g_emb[33554432];
__device__ float g_nrm[33554432];
__device__ float g_pre[33554432];
__device__ float g_q[16777216];
__device__ float g_k[16777216];
__device__ float g_v[16777216];
__device__ float g_t[16777216];
__device__ float g_pu[HB * NSPLIT * 256 * 256];
__device__ float g_pl[HB * NSPLIT * 256 * 512];
__device__ float g_su[HB * 256 * 256];
__device__ float g_sl[HB * 256 * 512];

// ---------------------------------------------------------------------------
// Helpers
// ---------------------------------------------------------------------------
__device__ __forceinline__ float gelu_exact(float x) {
    return 0.5f * x * (1.0f + erff(x * 0.70710678118654752f));
}

__device__ __forceinline__ float block_reduce_sum(float v, float* sbuf) {
    int tid = threadIdx.x;
    sbuf[tid] = v;
    __syncthreads();
    for (int s = 128; s > 0; s >>= 1) {
        if (tid < s) sbuf[tid] += sbuf[tid + s];
        __syncthreads();
    }
    float r = sbuf[0];
    __syncthreads();
    return r;
}

__device__ __forceinline__ float block_reduce_max(float v, float* sbuf) {
    int tid = threadIdx.x;
    sbuf[tid] = v;
    __syncthreads();
    for (int s = 128; s > 0; s >>= 1) {
        if (tid < s) sbuf[tid] = fmaxf(sbuf[tid], sbuf[tid + s]);
        __syncthreads();
    }
    float r = sbuf[0];
    __syncthreads();
    return r;
}

// pack two fp32 -> 2 bf16 (rn) in one u32 (lo elem in low half)
__device__ __forceinline__ unsigned pk_hi(float a, float b) {
    __nv_bfloat162 t = __floats2bfloat162_rn(a, b);
    return *(unsigned*)&t;
}
__device__ __forceinline__ float bf_hi(float v) {
    return __bfloat162float(__float2bfloat16_rn(v));
}

__device__ __forceinline__ unsigned s2u(const void* p) {
    return (unsigned)__cvta_generic_to_shared(p);
}

__device__ __forceinline__ void ldm4(unsigned* r, unsigned addr) {
    asm volatile("ldmatrix.sync.aligned.m8n8.x4.shared.b16 {%0,%1,%2,%3}, [%4];"
                 : "=r"(r[0]), "=r"(r[1]), "=r"(r[2]), "=r"(r[3]) : "r"(addr));
}
__device__ __forceinline__ void ldm4t(unsigned* r, unsigned addr) {
    asm volatile("ldmatrix.sync.aligned.m8n8.x4.trans.shared.b16 {%0,%1,%2,%3}, [%4];"
                 : "=r"(r[0]), "=r"(r[1]), "=r"(r[2]), "=r"(r[3]) : "r"(addr));
}
__device__ __forceinline__ void mma_bf16(float* c, const unsigned* a, unsigned b0, unsigned b1) {
    asm volatile(
        "mma.sync.aligned.m16n8k16.row.col.f32.bf16.bf16.f32 "
        "{%0,%1,%2,%3},{%4,%5,%6,%7},{%8,%9},{%0,%1,%2,%3};"
        : "+f"(c[0]), "+f"(c[1]), "+f"(c[2]), "+f"(c[3])
        : "r"(a[0]), "r"(a[1]), "r"(a[2]), "r"(a[3]), "r"(b0), "r"(b1));
}

// split 16 fp32 into packed bf16 hi[8], lo[8] u32 words
__device__ __forceinline__ void split16(const float* v, unsigned* h, unsigned* l) {
#pragma unroll
    for (int i = 0; i < 8; i++) {
        float a = v[2 * i], b = v[2 * i + 1];
        float ah = bf_hi(a), bh = bf_hi(b);
        h[i] = pk_hi(a, b);
        l[i] = pk_hi(a - ah, b - bh);
    }
}

#define PA 40    // smem pitch (bf16) for [row][k] operand tiles
#define PB 136   // smem pitch (bf16) for [k][n] B tiles

// ---------------------------------------------------------------------------
// conv1x1 GEMM via bf16x3 tensor-core: C[b](256 x 16384) = A(256xK) @ B[b](K x 16384)
// fp32 in, fp32 out. Block 128x128x32, 8 warps (2x4), warp tile 64x32.
// epi: 0 none, 1 gelu, 2 +R
// ---------------------------------------------------------------------------
__global__ __launch_bounds__(256)
void gemm_tc(const float* __restrict__ A, size_t aBs,
             const float* __restrict__ Bm, size_t bBs,
             float* __restrict__ C, size_t cBs,
             const float* __restrict__ R, size_t rBs,
             int K, int epi) {
    __shared__ __align__(16) __nv_bfloat16 smA[2][128 * PA];
    __shared__ __align__(16) __nv_bfloat16 smB[2][32 * PB];

    int b = blockIdx.z;
    A += (size_t)b * aBs;
    Bm += (size_t)b * bBs;
    C += (size_t)b * cBs;
    if (R) R += (size_t)b * rBs;

    int tid = threadIdx.x;
    int wid = tid >> 5, lane = tid & 31;
    int wm = wid & 1, wn = wid >> 1;
    int oBase = blockIdx.y * 128, nBase = blockIdx.x * 128;

    int lr = tid >> 1, lk = (tid & 1) * 16;   // A loader: row, k-offset
    int brr = tid >> 3, bn = (tid & 7) * 16;  // B loader: k-row, n-offset

    const float* Ap = A + (size_t)(oBase + lr) * K + lk;
    const float* Bp = Bm + (size_t)brr * GN + nBase + bn;

    float acc[4][4][4];
#pragma unroll
    for (int i = 0; i < 4; i++)
#pragma unroll
        for (int j = 0; j < 4; j++)
#pragma unroll
            for (int q = 0; q < 4; q++) acc[i][j][q] = 0.0f;

    float4 pa[4], pb[4];
#pragma unroll
    for (int i = 0; i < 4; i++) {
        pa[i] = ((const float4*)Ap)[i];
        pb[i] = ((const float4*)Bp)[i];
    }

    // frag base addresses (lane-dependent parts)
    unsigned aRow = (unsigned)(wm * 64 + (lane & 15));          // + mt*16
    unsigned aKof = (unsigned)((lane >> 4) * 8);                // + ks
    unsigned bKrow = (unsigned)((lane & 7) + ((lane >> 3) & 1) * 8);  // + ks
    unsigned bNcol = (unsigned)(wn * 32 + ((lane >> 4) & 1) * 8);     // + nt2*16

    int KT = K >> 5;
    for (int t = 0; t < KT; t++) {
        // split-convert and store to smem
        {
            unsigned h[8], l[8];
            split16((const float*)pa, h, l);
            unsigned off = lr * PA + lk;
            *(uint4*)&smA[0][off] = make_uint4(h[0], h[1], h[2], h[3]);
            *(uint4*)&smA[0][off + 8] = make_uint4(h[4], h[5], h[6], h[7]);
            *(uint4*)&smA[1][off] = make_uint4(l[0], l[1], l[2], l[3]);
            *(uint4*)&smA[1][off + 8] = make_uint4(l[4], l[5], l[6], l[7]);
            split16((const float*)pb, h, l);
            off = brr * PB + bn;
            *(uint4*)&smB[0][off] = make_uint4(h[0], h[1], h[2], h[3]);
            *(uint4*)&smB[0][off + 8] = make_uint4(h[4], h[5], h[6], h[7]);
            *(uint4*)&smB[1][off] = make_uint4(l[0], l[1], l[2], l[3]);
            *(uint4*)&smB[1][off + 8] = make_uint4(l[4], l[5], l[6], l[7]);
        }
        __syncthreads();

        if (t + 1 < KT) {
            Ap += 32;
            Bp += (size_t)32 * GN;
#pragma unroll
            for (int i = 0; i < 4; i++) {
                pa[i] = ((const float4*)Ap)[i];
                pb[i] = ((const float4*)Bp)[i];
            }
        }

#pragma unroll
        for (int ks = 0; ks < 32; ks += 16) {
            unsigned ah[4][4], bh[2][4];
#pragma unroll
            for (int mt = 0; mt < 4; mt++)
                ldm4(ah[mt], s2u(&smA[0][(aRow + mt * 16) * PA + ks + aKof]));
#pragma unroll
            for (int nt2 = 0; nt2 < 2; nt2++)
                ldm4t(bh[nt2], s2u(&smB[0][(bKrow + ks) * PB + bNcol + nt2 * 16]));
#pragma unroll
            for (int mt = 0; mt < 4; mt++)
#pragma unroll
                for (int nt = 0; nt < 4; nt++)
                    mma_bf16(acc[mt][nt], ah[mt], bh[nt >> 1][(nt & 1) * 2],
                             bh[nt >> 1][(nt & 1) * 2 + 1]);
            unsigned bl[2][4];
#pragma unroll
            for (int nt2 = 0; nt2 < 2; nt2++)
                ldm4t(bl[nt2], s2u(&smB[1][(bKrow + ks) * PB + bNcol + nt2 * 16]));
#pragma unroll
            for (int mt = 0; mt < 4; mt++)
#pragma unroll
                for (int nt = 0; nt < 4; nt++)
                    mma_bf16(acc[mt][nt], ah[mt], bl[nt >> 1][(nt & 1) * 2],
                             bl[nt >> 1][(nt & 1) * 2 + 1]);
            unsigned al[4][4];
#pragma unroll
            for (int mt = 0; mt < 4; mt++)
                ldm4(al[mt], s2u(&smA[1][(aRow + mt * 16) * PA + ks + aKof]));
#pragma unroll
            for (int mt = 0; mt < 4; mt++)
#pragma unroll
                for (int nt = 0; nt < 4; nt++)
                    mma_bf16(acc[mt][nt], al[mt], bh[nt >> 1][(nt & 1) * 2],
                             bh[nt >> 1][(nt & 1) * 2 + 1]);
        }
        __syncthreads();
    }

    // epilogue
    int g = lane >> 2, tg = lane & 3;
#pragma unroll
    for (int mt = 0; mt < 4; mt++) {
#pragma unroll
        for (int nt = 0; nt < 4; nt++) {
            int r0 = oBase + wm * 64 + mt * 16 + g;
            int col = nBase + wn * 32 + nt * 8 + tg * 2;
            float* c = acc[mt][nt];
#pragma unroll
            for (int h = 0; h < 2; h++) {
                int rr = r0 + h * 8;
                size_t base = (size_t)rr * GN + col;
                float o0 = c[2 * h], o1 = c[2 * h + 1];
                if (epi == 2) {
                    float2 rv = *(const float2*)&R[base];
                    o0 += rv.x; o1 += rv.y;
                } else if (epi == 1) {
                    o0 = gelu_exact(o0); o1 = gelu_exact(o1);
                }
                *(float2*)&C[base] = make_float2(o0, o1);
            }
        }
    }
}

// ---------------------------------------------------------------------------
// NT score GEMM via bf16x3: P[b][s][i][j] = sum_{n in chunk s} Q[i][n] K[j][n]
// Block 128(i) x 128(j) x 32(n). Both operands K-major -> non-trans ldmatrix.
// grid: (J/128, 2, HB*NSPLIT)
// ---------------------------------------------------------------------------
__global__ __launch_bounds__(256)
void gemmnt_tc(const float* __restrict__ Q, size_t qBs,
               const float* __restrict__ Km, size_t kBs,
               float* __restrict__ P, int J) {
    __shared__ __align__(16) __nv_bfloat16 smQ[2][128 * PA];
    __shared__ __align__(16) __nv_bfloat16 smK[2][128 * PA];

    int z = blockIdx.z;
    int b = z / NSPLIT;
    int s = z % NSPLIT;
    Q += (size_t)b * qBs;
    Km += (size_t)b * kBs;

    int tid = threadIdx.x;
    int wid = tid >> 5, lane = tid & 31;
    int wm = wid & 1, wn = wid >> 1;
    int iBase = blockIdx.y * 128, jBase = blockIdx.x * 128;

    int lr = tid >> 1, lk = (tid & 1) * 16;
    const int chunk = GN / NSPLIT;      // 1024
    int n0 = s * chunk;

    const float* Qp = Q + (size_t)(iBase + lr) * GN + n0 + lk;
    const float* Kp = Km + (size_t)(jBase + lr) * GN + n0 + lk;

    float acc[4][4][4];
#pragma unroll
    for (int i = 0; i < 4; i++)
#pragma unroll
        for (int j = 0; j < 4; j++)
#pragma unroll
            for (int q = 0; q < 4; q++) acc[i][j][q] = 0.0f;

    float4 pq[4], pk[4];
#pragma unroll
    for (int i = 0; i < 4; i++) {
        pq[i] = ((const float4*)Qp)[i];
        pk[i] = ((const float4*)Kp)[i];
    }

    unsigned aRow = (unsigned)(wm * 64 + (lane & 15));
    unsigned aKof = (unsigned)((lane >> 4) * 8);
    // B (K operand) non-trans mapping: row j, k-offset
    unsigned bJrow = (unsigned)(wn * 32 + (lane & 7) + ((lane >> 4) & 1) * 8);  // + nt2*16
    unsigned bKof = (unsigned)(((lane >> 3) & 1) * 8);                          // + ks

    int KT = chunk >> 5;
    for (int t = 0; t < KT; t++) {
        {
            unsigned h[8], l[8];
            split16((const float*)pq, h, l);
            unsigned off = lr * PA + lk;
            *(uint4*)&smQ[0][off] = make_uint4(h[0], h[1], h[2], h[3]);
            *(uint4*)&smQ[0][off + 8] = make_uint4(h[4], h[5], h[6], h[7]);
            *(uint4*)&smQ[1][off] = make_uint4(l[0], l[1], l[2], l[3]);
            *(uint4*)&smQ[1][off + 8] = make_uint4(l[4], l[5], l[6], l[7]);
            split16((const float*)pk, h, l);
            *(uint4*)&smK[0][off] = make_uint4(h[0], h[1], h[2], h[3]);
            *(uint4*)&smK[0][off + 8] = make_uint4(h[4], h[5], h[6], h[7]);
            *(uint4*)&smK[1][off] = make_uint4(l[0], l[1], l[2], l[3]);
            *(uint4*)&smK[1][off + 8] = make_uint4(l[4], l[5], l[6], l[7]);
        }
        __syncthreads();

        if (t + 1 < KT) {
            Qp += 32;
            Kp += 32;
#pragma unroll
            for (int i = 0; i < 4; i++) {
                pq[i] = ((const float4*)Qp)[i];
                pk[i] = ((const float4*)Kp)[i];
            }
        }

#pragma unroll
        for (int ks = 0; ks < 32; ks += 16) {
            unsigned ah[4][4], bh[2][4];
#pragma unroll
            for (int mt = 0; mt < 4; mt++)
                ldm4(ah[mt], s2u(&smQ[0][(aRow + mt * 16) * PA + ks + aKof]));
#pragma unroll
            for (int nt2 = 0; nt2 < 2; nt2++)
                ldm4(bh[nt2], s2u(&smK[0][(bJrow + nt2 * 16) * PA + ks + bKof]));
#pragma unroll
            for (int mt = 0; mt < 4; mt++)
#pragma unroll
                for (int nt = 0; nt < 4; nt++)
                    mma_bf16(acc[mt][nt], ah[mt], bh[nt >> 1][(nt & 1) * 2],
                             bh[nt >> 1][(nt & 1) * 2 + 1]);
            unsigned bl[2][4];
#pragma unroll
            for (int nt2 = 0; nt2 < 2; nt2++)
                ldm4(bl[nt2], s2u(&smK[1][(bJrow + nt2 * 16) * PA + ks + bKof]));
#pragma unroll
            for (int mt = 0; mt < 4; mt++)
#pragma unroll
                for (int nt = 0; nt < 4; nt++)
                    mma_bf16(acc[mt][nt], ah[mt], bl[nt >> 1][(nt & 1) * 2],
                             bl[nt >> 1][(nt & 1) * 2 + 1]);
            unsigned al[4][4];
#pragma unroll
            for (int mt = 0; mt < 4; mt++)
                ldm4(al[mt], s2u(&smQ[1][(aRow + mt * 16) * PA + ks + aKof]));
#pragma unroll
            for (int mt = 0; mt < 4; mt++)
#pragma unroll
                for (int nt = 0; nt < 4; nt++)
                    mma_bf16(acc[mt][nt], al[mt], bh[nt >> 1][(nt & 1) * 2],
                             bh[nt >> 1][(nt & 1) * 2 + 1]);
        }
        __syncthreads();
    }

    int g = lane >> 2, tg = lane & 3;
#pragma unroll
    for (int mt = 0; mt < 4; mt++) {
#pragma unroll
        for (int nt = 0; nt < 4; nt++) {
            int r0 = iBase + wm * 64 + mt * 16 + g;
            int col = jBase + wn * 32 + nt * 8 + tg * 2;
            float* c = acc[mt][nt];
#pragma unroll
            for (int h = 0; h < 2; h++) {
                int rr = r0 + h * 8;
                size_t base = ((size_t)z * 256 + rr) * J + col;
                *(float2*)&P[base] = make_float2(c[2 * h], c[2 * h + 1]);
            }
        }
    }
}

// ---------------------------------------------------------------------------
// Instance-norm over rows of length GN with optional per-channel affine.
// ---------------------------------------------------------------------------
__global__ __launch_bounds__(256)
void inorm_rows(const float* __restrict__ X, float* __restrict__ Y,
                const float* __restrict__ gamma, const float* __restrict__ beta) {
    __shared__ float sbuf[256];
    int row = blockIdx.x;
    int cch = row & (ECH - 1);
    const float4* xr = (const float4*)(X + (size_t)row * GN);
    float4* yr = (float4*)(Y + (size_t)row * GN);

    float s = 0.0f, ss = 0.0f;
    for (int idx = threadIdx.x; idx < GN / 4; idx += 256) {
        float4 v = xr[idx];
        s += v.x + v.y + v.z + v.w;
        ss += v.x * v.x + v.y * v.y + v.z * v.z + v.w * v.w;
    }
    float tot = block_reduce_sum(s, sbuf);
    float tot2 = block_reduce_sum(ss, sbuf);
    const float inv = 1.0f / (float)GN;
    float mu = tot * inv;
    float var = tot2 * inv - mu * mu;
    float rstd = rsqrtf(var + 1e-5f);
    float g = gamma ? gamma[cch] : 1.0f;
    float be = beta ? beta[cch] : 0.0f;
    float a = rstd * g;
    float bb = be - mu * a;

    for (int idx = threadIdx.x; idx < GN / 4; idx += 256) {
        float4 v = xr[idx];
        v.x = v.x * a + bb; v.y = v.y * a + bb;
        v.z = v.z * a + bb; v.w = v.w * a + bb;
        yr[idx] = v;
    }
}

// ---------------------------------------------------------------------------
// Reduce NSPLIT partials -> scale -> inorm (no affine) -> softmax.
// ---------------------------------------------------------------------------
__global__ __launch_bounds__(256)
void inorm_softmax(const float* __restrict__ P, float* __restrict__ S,
                   int J, float scale) {
    __shared__ float rowbuf[512];
    __shared__ float sbuf[256];
    int row = blockIdx.x;
    int b = row >> 8;
    int i = row & 255;
    int tid = threadIdx.x;

    for (int j = tid; j < J; j += 256) {
        float v = 0.0f;
#pragma unroll
        for (int s = 0; s < NSPLIT; s++)
            v += P[(((size_t)(b * NSPLIT + s) * 256) + i) * J + j];
        rowbuf[j] = v * scale;
    }
    __syncthreads();

    float ls = 0.0f;
    for (int j = tid; j < J; j += 256) ls += rowbuf[j];
    float mean = block_reduce_sum(ls, sbuf) / (float)J;

    float lv = 0.0f;
    for (int j = tid; j < J; j += 256) {
        float d = rowbuf[j] - mean;
        lv += d * d;
    }
    float var = block_reduce_sum(lv, sbuf) / (float)J;
    float rstd = rsqrtf(var + 1e-5f);

    float lm = -1e30f;
    for (int j = tid; j < J; j += 256) {
        float tt = (rowbuf[j] - mean) * rstd;
        rowbuf[j] = tt;
        lm = fmaxf(lm, tt);
    }
    float mx = block_reduce_max(lm, sbuf);

    float le = 0.0f;
    for (int j = tid; j < J; j += 256) {
        float e = expf(rowbuf[j] - mx);
        rowbuf[j] = e;
        le += e;
    }
    float denom = block_reduce_sum(le, sbuf);
    float rden = 1.0f / denom;

    for (int j = tid; j < J; j += 256)
        S[((size_t)b * 256 + i) * J + j] = rowbuf[j] * rden;
}

// ---------------------------------------------------------------------------
// Launch
// ---------------------------------------------------------------------------
extern "C" void kernel_launch(void* const* d_in, const int* in_sizes, int n_in,
                              void* d_out, int out_size) {
    const float* feat  = (const float*)d_in[0];
    const float* kv    = (const float*)d_in[1];
    const float* w_in  = (const float*)d_in[2];
    const float* w_out = (const float*)d_in[3];
    const float* wq_sa = (const float*)d_in[4];
    const float* wk_sa = (const float*)d_in[5];
    const float* wv_sa = (const float*)d_in[6];
    const float* wo_sa = (const float*)d_in[7];
    const float* wq_ca = (const float*)d_in[8];
    const float* wo_ca = (const float*)d_in[9];
    const float* ag    = (const float*)d_in[10];
    const float* ab    = (const float*)d_in[11];
    const float* eg    = (const float*)d_in[12];
    const float* eb    = (const float*)d_in[13];
    float* out = (float*)d_out;

    float *emb, *nrm, *pre, *q, *k, *v, *t, *pu, *pl, *su, *sl;
    cudaGetSymbolAddress((void**)&emb, g_emb);
    cudaGetSymbolAddress((void**)&nrm, g_nrm);
    cudaGetSymbolAddress((void**)&pre, g_pre);
    cudaGetSymbolAddress((void**)&q,   g_q);
    cudaGetSymbolAddress((void**)&k,   g_k);
    cudaGetSymbolAddress((void**)&v,   g_v);
    cudaGetSymbolAddress((void**)&t,   g_t);
    cudaGetSymbolAddress((void**)&pu,  g_pu);
    cudaGetSymbolAddress((void**)&pl,  g_pl);
    cudaGetSymbolAddress((void**)&su,  g_su);
    cudaGetSymbolAddress((void**)&sl,  g_sl);

    const float scale = 1.0f / 128.0f;   // N^{-1/2}
    dim3 blk(256);
    dim3 g8(GN / 128, 2, 8);
    dim3 g4(GN / 128, 2, 4);

    // 1. emb = gelu(w_in @ x)
    gemm_tc<<<g8, blk>>>(w_in, 0, feat, BSTR, emb, BSTR, nullptr, 0, 256, 1);
    // 2. nrm = inorm(emb, attn_gamma, attn_beta)
    inorm_rows<<<NB * ECH, blk>>>(emb, nrm, ag, ab);
    // 3-5. upper Q/K/V
    gemm_tc<<<g4, blk>>>(wq_sa, 0, nrm + TOT4, BSTR, q, BSTR, nullptr, 0, 256, 0);
    gemm_tc<<<g4, blk>>>(wk_sa, 0, nrm + TOT4, BSTR, k, BSTR, nullptr, 0, 256, 0);
    gemm_tc<<<g4, blk>>>(wv_sa, 0, nrm + TOT4, BSTR, v, BSTR, nullptr, 0, 256, 0);
    // 6. upper score partials
    gemmnt_tc<<<dim3(2, 2, HB * NSPLIT), blk>>>(q, BSTR, k, BSTR, pu, 256);
    // 7. reduce + inorm + softmax
    inorm_softmax<<<HB * 256, blk>>>(pu, su, 256, scale);
    // 8. attn @ V
    gemm_tc<<<g4, blk>>>(su, 256 * 256, v, BSTR, t, BSTR, nullptr, 0, 256, 0);
    // 9. sa_u = wo_sa @ t + emb_u
    gemm_tc<<<g4, blk>>>(wo_sa, 0, t, BSTR, pre + TOT4, BSTR, emb + TOT4, BSTR, 256, 2);
    // 10. lower Ql
    gemm_tc<<<g4, blk>>>(wq_ca, 0, nrm, BSTR, q, BSTR, nullptr, 0, 256, 0);
    // 11. lower score partials (kv shared across batches)
    gemmnt_tc<<<dim3(4, 2, HB * NSPLIT), blk>>>(q, BSTR, kv, 0, pl, 512);
    // 12. reduce + inorm + softmax (J=512)
    inorm_softmax<<<HB * 256, blk>>>(pl, sl, 512, scale);
    // 13. ca = attn_l @ kv (K=512)
    gemm_tc<<<g4, blk>>>(sl, 256 * 512, kv, 0, t, BSTR, nullptr, 0, 512, 0);
    // 14. ca_l = wo_ca @ ca + emb_l
    gemm_tc<<<g4, blk>>>(wo_ca, 0, t, BSTR, pre, BSTR, emb, BSTR, 256, 2);
    // 15. nrm2 = inorm(pre, enc_gamma, enc_beta)
    inorm_rows<<<NB * ECH, blk>>>(pre, nrm, eg, eb);
    // 16. out = gelu(w_out @ nrm2)
    gemm_tc<<<g8, blk>>>(w_out, 0, nrm, BSTR, out, BSTR, nullptr, 0, 256, 1);
}

// round 4
// speedup vs baseline: 2.7712x; 1.0005x over previous
#include <cuda_runtime.h>
#include <cuda_bf16.h>
#include <math.h>

// ---------------------------------------------------------------------------
// Problem constants
// ---------------------------------------------------------------------------
#define GN 16384                  // spatial N = H*W
#define ECH 256                   // embed channels (= C)
#define NB 8                      // total batches (twoB)
#define HB 4                      // half batch
#define NSPLIT 16                 // n-split for NT score GEMMs
static const size_t BSTR = (size_t)ECH * GN;
static const size_t TOT4 = (size_t)HB * BSTR;

// ---------------------------------------------------------------------------
// Scratch
// ---------------------------------------------------------------------------
__device__ float g_emb[33554432];
__device__ float g_nrm[33554432];
__device__ float g_pre[33554432];
__device__ float g_q[16777216];
__device__ float g_k[16777216];
__device__ float g_v[16777216];
__device__ float g_t[16777216];
__device__ float g_pu[HB * NSPLIT * 256 * 256];
__device__ float g_pl[HB * NSPLIT * 256 * 512];
__device__ float g_su[HB * 256 * 256];
__device__ float g_sl[HB * 256 * 512];

// ---------------------------------------------------------------------------
// Helpers
// ---------------------------------------------------------------------------
__device__ __forceinline__ float gelu_exact(float x) {
    return 0.5f * x * (1.0f + erff(x * 0.70710678118654752f));
}

__device__ __forceinline__ float block_reduce_sum(float v, float* sbuf) {
    int tid = threadIdx.x;
    sbuf[tid] = v;
    __syncthreads();
    for (int s = 128; s > 0; s >>= 1) {
        if (tid < s) sbuf[tid] += sbuf[tid + s];
        __syncthreads();
    }
    float r = sbuf[0];
    __syncthreads();
    return r;
}

__device__ __forceinline__ float block_reduce_max(float v, float* sbuf) {
    int tid = threadIdx.x;
    sbuf[tid] = v;
    __syncthreads();
    for (int s = 128; s > 0; s >>= 1) {
        if (tid < s) sbuf[tid] = fmaxf(sbuf[tid], sbuf[tid + s]);
        __syncthreads();
    }
    float r = sbuf[0];
    __syncthreads();
    return r;
}

// pack two fp32 -> 2 bf16 (rn) in one u32 (lo elem in low half)
__device__ __forceinline__ unsigned pk_hi(float a, float b) {
    __nv_bfloat162 t = __floats2bfloat162_rn(a, b);
    return *(unsigned*)&t;
}
__device__ __forceinline__ float bf_hi(float v) {
    return __bfloat162float(__float2bfloat16_rn(v));
}

__device__ __forceinline__ unsigned s2u(const void* p) {
    return (unsigned)__cvta_generic_to_shared(p);
}

__device__ __forceinline__ void ldm4(unsigned* r, unsigned addr) {
    asm volatile("ldmatrix.sync.aligned.m8n8.x4.shared.b16 {%0,%1,%2,%3}, [%4];"
                 : "=r"(r[0]), "=r"(r[1]), "=r"(r[2]), "=r"(r[3]) : "r"(addr));
}
__device__ __forceinline__ void ldm4t(unsigned* r, unsigned addr) {
    asm volatile("ldmatrix.sync.aligned.m8n8.x4.trans.shared.b16 {%0,%1,%2,%3}, [%4];"
                 : "=r"(r[0]), "=r"(r[1]), "=r"(r[2]), "=r"(r[3]) : "r"(addr));
}
__device__ __forceinline__ void mma_bf16(float* c, const unsigned* a, unsigned b0, unsigned b1) {
    asm volatile(
        "mma.sync.aligned.m16n8k16.row.col.f32.bf16.bf16.f32 "
        "{%0,%1,%2,%3},{%4,%5,%6,%7},{%8,%9},{%0,%1,%2,%3};"
        : "+f"(c[0]), "+f"(c[1]), "+f"(c[2]), "+f"(c[3])
        : "r"(a[0]), "r"(a[1]), "r"(a[2]), "r"(a[3]), "r"(b0), "r"(b1));
}

// split 16 fp32 into packed bf16 hi[8], lo[8] u32 words
__device__ __forceinline__ void split16(const float* v, unsigned* h, unsigned* l) {
#pragma unroll
    for (int i = 0; i < 8; i++) {
        float a = v[2 * i], b = v[2 * i + 1];
        float ah = bf_hi(a), bh = bf_hi(b);
        h[i] = pk_hi(a, b);
        l[i] = pk_hi(a - ah, b - bh);
    }
}

#define PA 40    // smem pitch (bf16) for [row][k] operand tiles
#define PB 136   // smem pitch (bf16) for [k][n] B tiles

// ---------------------------------------------------------------------------
// conv1x1 GEMM via bf16x3 tensor-core: C[b](256 x 16384) = A(256xK) @ B[b](K x 16384)
// fp32 in, fp32 out. Block 128x128x32, 8 warps (2x4), warp tile 64x32.
// epi: 0 none, 1 gelu, 2 +R
// ---------------------------------------------------------------------------
__global__ __launch_bounds__(256)
void gemm_tc(const float* __restrict__ A, size_t aBs,
             const float* __restrict__ Bm, size_t bBs,
             float* __restrict__ C, size_t cBs,
             const float* __restrict__ R, size_t rBs,
             int K, int epi) {
    __shared__ __align__(16) __nv_bfloat16 smA[2][128 * PA];
    __shared__ __align__(16) __nv_bfloat16 smB[2][32 * PB];

    int b = blockIdx.z;
    A += (size_t)b * aBs;
    Bm += (size_t)b * bBs;
    C += (size_t)b * cBs;
    if (R) R += (size_t)b * rBs;

    int tid = threadIdx.x;
    int wid = tid >> 5, lane = tid & 31;
    int wm = wid & 1, wn = wid >> 1;
    int oBase = blockIdx.y * 128, nBase = blockIdx.x * 128;

    int lr = tid >> 1, lk = (tid & 1) * 16;   // A loader: row, k-offset
    int brr = tid >> 3, bn = (tid & 7) * 16;  // B loader: k-row, n-offset

    const float* Ap = A + (size_t)(oBase + lr) * K + lk;
    const float* Bp = Bm + (size_t)brr * GN + nBase + bn;

    float acc[4][4][4];
#pragma unroll
    for (int i = 0; i < 4; i++)
#pragma unroll
        for (int j = 0; j < 4; j++)
#pragma unroll
            for (int q = 0; q < 4; q++) acc[i][j][q] = 0.0f;

    float4 pa[4], pb[4];
#pragma unroll
    for (int i = 0; i < 4; i++) {
        pa[i] = ((const float4*)Ap)[i];
        pb[i] = ((const float4*)Bp)[i];
    }

    // frag base addresses (lane-dependent parts)
    unsigned aRow = (unsigned)(wm * 64 + (lane & 15));          // + mt*16
    unsigned aKof = (unsigned)((lane >> 4) * 8);                // + ks
    unsigned bKrow = (unsigned)((lane & 7) + ((lane >> 3) & 1) * 8);  // + ks
    unsigned bNcol = (unsigned)(wn * 32 + ((lane >> 4) & 1) * 8);     // + nt2*16

    int KT = K >> 5;
    for (int t = 0; t < KT; t++) {
        // split-convert and store to smem
        {
            unsigned h[8], l[8];
            split16((const float*)pa, h, l);
            unsigned off = lr * PA + lk;
            *(uint4*)&smA[0][off] = make_uint4(h[0], h[1], h[2], h[3]);
            *(uint4*)&smA[0][off + 8] = make_uint4(h[4], h[5], h[6], h[7]);
            *(uint4*)&smA[1][off] = make_uint4(l[0], l[1], l[2], l[3]);
            *(uint4*)&smA[1][off + 8] = make_uint4(l[4], l[5], l[6], l[7]);
            split16((const float*)pb, h, l);
            off = brr * PB + bn;
            *(uint4*)&smB[0][off] = make_uint4(h[0], h[1], h[2], h[3]);
            *(uint4*)&smB[0][off + 8] = make_uint4(h[4], h[5], h[6], h[7]);
            *(uint4*)&smB[1][off] = make_uint4(l[0], l[1], l[2], l[3]);
            *(uint4*)&smB[1][off + 8] = make_uint4(l[4], l[5], l[6], l[7]);
        }
        __syncthreads();

        if (t + 1 < KT) {
            Ap += 32;
            Bp += (size_t)32 * GN;
#pragma unroll
            for (int i = 0; i < 4; i++) {
                pa[i] = ((const float4*)Ap)[i];
                pb[i] = ((const float4*)Bp)[i];
            }
        }

#pragma unroll
        for (int ks = 0; ks < 32; ks += 16) {
            unsigned ah[4][4], bh[2][4];
#pragma unroll
            for (int mt = 0; mt < 4; mt++)
                ldm4(ah[mt], s2u(&smA[0][(aRow + mt * 16) * PA + ks + aKof]));
#pragma unroll
            for (int nt2 = 0; nt2 < 2; nt2++)
                ldm4t(bh[nt2], s2u(&smB[0][(bKrow + ks) * PB + bNcol + nt2 * 16]));
#pragma unroll
            for (int mt = 0; mt < 4; mt++)
#pragma unroll
                for (int nt = 0; nt < 4; nt++)
                    mma_bf16(acc[mt][nt], ah[mt], bh[nt >> 1][(nt & 1) * 2],
                             bh[nt >> 1][(nt & 1) * 2 + 1]);
            unsigned bl[2][4];
#pragma unroll
            for (int nt2 = 0; nt2 < 2; nt2++)
                ldm4t(bl[nt2], s2u(&smB[1][(bKrow + ks) * PB + bNcol + nt2 * 16]));
#pragma unroll
            for (int mt = 0; mt < 4; mt++)
#pragma unroll
                for (int nt = 0; nt < 4; nt++)
                    mma_bf16(acc[mt][nt], ah[mt], bl[nt >> 1][(nt & 1) * 2],
                             bl[nt >> 1][(nt & 1) * 2 + 1]);
            unsigned al[4][4];
#pragma unroll
            for (int mt = 0; mt < 4; mt++)
                ldm4(al[mt], s2u(&smA[1][(aRow + mt * 16) * PA + ks + aKof]));
#pragma unroll
            for (int mt = 0; mt < 4; mt++)
#pragma unroll
                for (int nt = 0; nt < 4; nt++)
                    mma_bf16(acc[mt][nt], al[mt], bh[nt >> 1][(nt & 1) * 2],
                             bh[nt >> 1][(nt & 1) * 2 + 1]);
        }
        __syncthreads();
    }

    // epilogue
    int g = lane >> 2, tg = lane & 3;
#pragma unroll
    for (int mt = 0; mt < 4; mt++) {
#pragma unroll
        for (int nt = 0; nt < 4; nt++) {
            int r0 = oBase + wm * 64 + mt * 16 + g;
            int col = nBase + wn * 32 + nt * 8 + tg * 2;
            float* c = acc[mt][nt];
#pragma unroll
            for (int h = 0; h < 2; h++) {
                int rr = r0 + h * 8;
                size_t base = (size_t)rr * GN + col;
                float o0 = c[2 * h], o1 = c[2 * h + 1];
                if (epi == 2) {
                    float2 rv = *(const float2*)&R[base];
                    o0 += rv.x; o1 += rv.y;
                } else if (epi == 1) {
                    o0 = gelu_exact(o0); o1 = gelu_exact(o1);
                }
                *(float2*)&C[base] = make_float2(o0, o1);
            }
        }
    }
}

// ---------------------------------------------------------------------------
// NT score GEMM via bf16x3: P[b][s][i][j] = sum_{n in chunk s} Q[i][n] K[j][n]
// Block 128(i) x 128(j) x 32(n). Both operands K-major -> non-trans ldmatrix.
// grid: (J/128, 2, HB*NSPLIT)
// ---------------------------------------------------------------------------
__global__ __launch_bounds__(256)
void gemmnt_tc(const float* __restrict__ Q, size_t qBs,
               const float* __restrict__ Km, size_t kBs,
               float* __restrict__ P, int J) {
    __shared__ __align__(16) __nv_bfloat16 smQ[2][128 * PA];
    __shared__ __align__(16) __nv_bfloat16 smK[2][128 * PA];

    int z = blockIdx.z;
    int b = z / NSPLIT;
    int s = z % NSPLIT;
    Q += (size_t)b * qBs;
    Km += (size_t)b * kBs;

    int tid = threadIdx.x;
    int wid = tid >> 5, lane = tid & 31;
    int wm = wid & 1, wn = wid >> 1;
    int iBase = blockIdx.y * 128, jBase = blockIdx.x * 128;

    int lr = tid >> 1, lk = (tid & 1) * 16;
    const int chunk = GN / NSPLIT;      // 1024
    int n0 = s * chunk;

    const float* Qp = Q + (size_t)(iBase + lr) * GN + n0 + lk;
    const float* Kp = Km + (size_t)(jBase + lr) * GN + n0 + lk;

    float acc[4][4][4];
#pragma unroll
    for (int i = 0; i < 4; i++)
#pragma unroll
        for (int j = 0; j < 4; j++)
#pragma unroll
            for (int q = 0; q < 4; q++) acc[i][j][q] = 0.0f;

    float4 pq[4], pk[4];
#pragma unroll
    for (int i = 0; i < 4; i++) {
        pq[i] = ((const float4*)Qp)[i];
        pk[i] = ((const float4*)Kp)[i];
    }

    unsigned aRow = (unsigned)(wm * 64 + (lane & 15));
    unsigned aKof = (unsigned)((lane >> 4) * 8);
    // B (K operand) non-trans mapping: row j, k-offset
    unsigned bJrow = (unsigned)(wn * 32 + (lane & 7) + ((lane >> 4) & 1) * 8);  // + nt2*16
    unsigned bKof = (unsigned)(((lane >> 3) & 1) * 8);                          // + ks

    int KT = chunk >> 5;
    for (int t = 0; t < KT; t++) {
        {
            unsigned h[8], l[8];
            split16((const float*)pq, h, l);
            unsigned off = lr * PA + lk;
            *(uint4*)&smQ[0][off] = make_uint4(h[0], h[1], h[2], h[3]);
            *(uint4*)&smQ[0][off + 8] = make_uint4(h[4], h[5], h[6], h[7]);
            *(uint4*)&smQ[1][off] = make_uint4(l[0], l[1], l[2], l[3]);
            *(uint4*)&smQ[1][off + 8] = make_uint4(l[4], l[5], l[6], l[7]);
            split16((const float*)pk, h, l);
            *(uint4*)&smK[0][off] = make_uint4(h[0], h[1], h[2], h[3]);
            *(uint4*)&smK[0][off + 8] = make_uint4(h[4], h[5], h[6], h[7]);
            *(uint4*)&smK[1][off] = make_uint4(l[0], l[1], l[2], l[3]);
            *(uint4*)&smK[1][off + 8] = make_uint4(l[4], l[5], l[6], l[7]);
        }
        __syncthreads();

        if (t + 1 < KT) {
            Qp += 32;
            Kp += 32;
#pragma unroll
            for (int i = 0; i < 4; i++) {
                pq[i] = ((const float4*)Qp)[i];
                pk[i] = ((const float4*)Kp)[i];
            }
        }

#pragma unroll
        for (int ks = 0; ks < 32; ks += 16) {
            unsigned ah[4][4], bh[2][4];
#pragma unroll
            for (int mt = 0; mt < 4; mt++)
                ldm4(ah[mt], s2u(&smQ[0][(aRow + mt * 16) * PA + ks + aKof]));
#pragma unroll
            for (int nt2 = 0; nt2 < 2; nt2++)
                ldm4(bh[nt2], s2u(&smK[0][(bJrow + nt2 * 16) * PA + ks + bKof]));
#pragma unroll
            for (int mt = 0; mt < 4; mt++)
#pragma unroll
                for (int nt = 0; nt < 4; nt++)
                    mma_bf16(acc[mt][nt], ah[mt], bh[nt >> 1][(nt & 1) * 2],
                             bh[nt >> 1][(nt & 1) * 2 + 1]);
            unsigned bl[2][4];
#pragma unroll
            for (int nt2 = 0; nt2 < 2; nt2++)
                ldm4(bl[nt2], s2u(&smK[1][(bJrow + nt2 * 16) * PA + ks + bKof]));
#pragma unroll
            for (int mt = 0; mt < 4; mt++)
#pragma unroll
                for (int nt = 0; nt < 4; nt++)
                    mma_bf16(acc[mt][nt], ah[mt], bl[nt >> 1][(nt & 1) * 2],
                             bl[nt >> 1][(nt & 1) * 2 + 1]);
            unsigned al[4][4];
#pragma unroll
            for (int mt = 0; mt < 4; mt++)
                ldm4(al[mt], s2u(&smQ[1][(aRow + mt * 16) * PA + ks + aKof]));
#pragma unroll
            for (int mt = 0; mt < 4; mt++)
#pragma unroll
                for (int nt = 0; nt < 4; nt++)
                    mma_bf16(acc[mt][nt], al[mt], bh[nt >> 1][(nt & 1) * 2],
                             bh[nt >> 1][(nt & 1) * 2 + 1]);
        }
        __syncthreads();
    }

    int g = lane >> 2, tg = lane & 3;
#pragma unroll
    for (int mt = 0; mt < 4; mt++) {
#pragma unroll
        for (int nt = 0; nt < 4; nt++) {
            int r0 = iBase + wm * 64 + mt * 16 + g;
            int col = jBase + wn * 32 + nt * 8 + tg * 2;
            float* c = acc[mt][nt];
#pragma unroll
            for (int h = 0; h < 2; h++) {
                int rr = r0 + h * 8;
                size_t base = ((size_t)z * 256 + rr) * J + col;
                *(float2*)&P[base] = make_float2(c[2 * h], c[2 * h + 1]);
            }
        }
    }
}

// ---------------------------------------------------------------------------
// Instance-norm over rows of length GN with optional per-channel affine.
// ---------------------------------------------------------------------------
__global__ __launch_bounds__(256)
void inorm_rows(const float* __restrict__ X, float* __restrict__ Y,
                const float* __restrict__ gamma, const float* __restrict__ beta) {
    __shared__ float sbuf[256];
    int row = blockIdx.x;
    int cch = row & (ECH - 1);
    const float4* xr = (const float4*)(X + (size_t)row * GN);
    float4* yr = (float4*)(Y + (size_t)row * GN);

    float s = 0.0f, ss = 0.0f;
    for (int idx = threadIdx.x; idx < GN / 4; idx += 256) {
        float4 v = xr[idx];
        s += v.x + v.y + v.z + v.w;
        ss += v.x * v.x + v.y * v.y + v.z * v.z + v.w * v.w;
    }
    float tot = block_reduce_sum(s, sbuf);
    float tot2 = block_reduce_sum(ss, sbuf);
    const float inv = 1.0f / (float)GN;
    float mu = tot * inv;
    float var = tot2 * inv - mu * mu;
    float rstd = rsqrtf(var + 1e-5f);
    float g = gamma ? gamma[cch] : 1.0f;
    float be = beta ? beta[cch] : 0.0f;
    float a = rstd * g;
    float bb = be - mu * a;

    for (int idx = threadIdx.x; idx < GN / 4; idx += 256) {
        float4 v = xr[idx];
        v.x = v.x * a + bb; v.y = v.y * a + bb;
        v.z = v.z * a + bb; v.w = v.w * a + bb;
        yr[idx] = v;
    }
}

// ---------------------------------------------------------------------------
// Reduce NSPLIT partials -> scale -> inorm (no affine) -> softmax.
// ---------------------------------------------------------------------------
__global__ __launch_bounds__(256)
void inorm_softmax(const float* __restrict__ P, float* __restrict__ S,
                   int J, float scale) {
    __shared__ float rowbuf[512];
    __shared__ float sbuf[256];
    int row = blockIdx.x;
    int b = row >> 8;
    int i = row & 255;
    int tid = threadIdx.x;

    for (int j = tid; j < J; j += 256) {
        float v = 0.0f;
#pragma unroll
        for (int s = 0; s < NSPLIT; s++)
            v += P[(((size_t)(b * NSPLIT + s) * 256) + i) * J + j];
        rowbuf[j] = v * scale;
    }
    __syncthreads();

    float ls = 0.0f;
    for (int j = tid; j < J; j += 256) ls += rowbuf[j];
    float mean = block_reduce_sum(ls, sbuf) / (float)J;

    float lv = 0.0f;
    for (int j = tid; j < J; j += 256) {
        float d = rowbuf[j] - mean;
        lv += d * d;
    }
    float var = block_reduce_sum(lv, sbuf) / (float)J;
    float rstd = rsqrtf(var + 1e-5f);

    float lm = -1e30f;
    for (int j = tid; j < J; j += 256) {
        float tt = (rowbuf[j] - mean) * rstd;
        rowbuf[j] = tt;
        lm = fmaxf(lm, tt);
    }
    float mx = block_reduce_max(lm, sbuf);

    float le = 0.0f;
    for (int j = tid; j < J; j += 256) {
        float e = expf(rowbuf[j] - mx);
        rowbuf[j] = e;
        le += e;
    }
    float denom = block_reduce_sum(le, sbuf);
    float rden = 1.0f / denom;

    for (int j = tid; j < J; j += 256)
        S[((size_t)b * 256 + i) * J + j] = rowbuf[j] * rden;
}

// ---------------------------------------------------------------------------
// Launch
// ---------------------------------------------------------------------------
extern "C" void kernel_launch(void* const* d_in, const int* in_sizes, int n_in,
                              void* d_out, int out_size) {
    const float* feat  = (const float*)d_in[0];
    const float* kv    = (const float*)d_in[1];
    const float* w_in  = (const float*)d_in[2];
    const float* w_out = (const float*)d_in[3];
    const float* wq_sa = (const float*)d_in[4];
    const float* wk_sa = (const float*)d_in[5];
    const float* wv_sa = (const float*)d_in[6];
    const float* wo_sa = (const float*)d_in[7];
    const float* wq_ca = (const float*)d_in[8];
    const float* wo_ca = (const float*)d_in[9];
    const float* ag    = (const float*)d_in[10];
    const float* ab    = (const float*)d_in[11];
    const float* eg    = (const float*)d_in[12];
    const float* eb    = (const float*)d_in[13];
    float* out = (float*)d_out;

    float *emb, *nrm, *pre, *q, *k, *v, *t, *pu, *pl, *su, *sl;
    cudaGetSymbolAddress((void**)&emb, g_emb);
    cudaGetSymbolAddress((void**)&nrm, g_nrm);
    cudaGetSymbolAddress((void**)&pre, g_pre);
    cudaGetSymbolAddress((void**)&q,   g_q);
    cudaGetSymbolAddress((void**)&k,   g_k);
    cudaGetSymbolAddress((void**)&v,   g_v);
    cudaGetSymbolAddress((void**)&t,   g_t);
    cudaGetSymbolAddress((void**)&pu,  g_pu);
    cudaGetSymbolAddress((void**)&pl,  g_pl);
    cudaGetSymbolAddress((void**)&su,  g_su);
    cudaGetSymbolAddress((void**)&sl,  g_sl);

    const float scale = 1.0f / 128.0f;   // N^{-1/2}
    dim3 blk(256);
    dim3 g8(GN / 128, 2, 8);
    dim3 g4(GN / 128, 2, 4);

    // 1. emb = gelu(w_in @ x)
    gemm_tc<<<g8, blk>>>(w_in, 0, feat, BSTR, emb, BSTR, nullptr, 0, 256, 1);
    // 2. nrm = inorm(emb, attn_gamma, attn_beta)
    inorm_rows<<<NB * ECH, blk>>>(emb, nrm, ag, ab);
    // 3-5. upper Q/K/V
    gemm_tc<<<g4, blk>>>(wq_sa, 0, nrm + TOT4, BSTR, q, BSTR, nullptr, 0, 256, 0);
    gemm_tc<<<g4, blk>>>(wk_sa, 0, nrm + TOT4, BSTR, k, BSTR, nullptr, 0, 256, 0);
    gemm_tc<<<g4, blk>>>(wv_sa, 0, nrm + TOT4, BSTR, v, BSTR, nullptr, 0, 256, 0);
    // 6. upper score partials
    gemmnt_tc<<<dim3(2, 2, HB * NSPLIT), blk>>>(q, BSTR, k, BSTR, pu, 256);
    // 7. reduce + inorm + softmax
    inorm_softmax<<<HB * 256, blk>>>(pu, su, 256, scale);
    // 8. attn @ V
    gemm_tc<<<g4, blk>>>(su, 256 * 256, v, BSTR, t, BSTR, nullptr, 0, 256, 0);
    // 9. sa_u = wo_sa @ t + emb_u
    gemm_tc<<<g4, blk>>>(wo_sa, 0, t, BSTR, pre + TOT4, BSTR, emb + TOT4, BSTR, 256, 2);
    // 10. lower Ql
    gemm_tc<<<g4, blk>>>(wq_ca, 0, nrm, BSTR, q, BSTR, nullptr, 0, 256, 0);
    // 11. lower score partials (kv shared across batches)
    gemmnt_tc<<<dim3(4, 2, HB * NSPLIT), blk>>>(q, BSTR, kv, 0, pl, 512);
    // 12. reduce + inorm + softmax (J=512)
    inorm_softmax<<<HB * 256, blk>>>(pl, sl, 512, scale);
    // 13. ca = attn_l @ kv (K=512)
    gemm_tc<<<g4, blk>>>(sl, 256 * 512, kv, 0, t, BSTR, nullptr, 0, 512, 0);
    // 14. ca_l = wo_ca @ ca + emb_l
    gemm_tc<<<g4, blk>>>(wo_ca, 0, t, BSTR, pre, BSTR, emb, BSTR, 256, 2);
    // 15. nrm2 = inorm(pre, enc_gamma, enc_beta)
    inorm_rows<<<NB * ECH, blk>>>(pre, nrm, eg, eb);
    // 16. out = gelu(w_out @ nrm2)
    gemm_tc<<<g8, blk>>>(w_out, 0, nrm, BSTR, out, BSTR, nullptr, 0, 256, 1);
}

// round 6
// speedup vs baseline: 3.4512x; 1.2454x over previous
#include <cuda_runtime.h>
#include <cuda_bf16.h>
#include <math.h>

#define GN 16384
#define ECH 256
#define NB 8
#define HB 4
#define NSPLIT 16
static const size_t BSTR = (size_t)ECH * GN;          // 4,194,304
static const size_t TOT4 = (size_t)HB * BSTR;
typedef __nv_bfloat16 bf16;
typedef __nv_bfloat162 bf162;

// ---------------- scratch ----------------
__device__ float g_emb[33554432];
__device__ float g_pre[33554432];
__device__ float g_pu[HB * NSPLIT * 256 * 256];
__device__ float g_plw[HB * NSPLIT * 256 * 512];
// bf16 hi/lo planes
__device__ bf16 g_fh[33554432], g_fl[33554432];       // feat split
__device__ bf16 g_nh[33554432], g_nl[33554432];       // norm split (reused)
__device__ bf16 g_qh[16777216], g_ql[16777216];
__device__ bf16 g_kh[16777216], g_kl[16777216];
__device__ bf16 g_vh[16777216], g_vl[16777216];
__device__ bf16 g_th[16777216], g_tl[16777216];
__device__ bf16 g_kvh[8388608], g_kvl[8388608];
__device__ bf16 g_suh[1048576], g_sul[1048576];       // su 262144 / sl 524288
__device__ bf16 g_slh[1048576], g_sll[1048576];
__device__ bf16 g_wh[524288], g_wl[524288];           // 8 x 65536 weight slots

// ---------------- helpers ----------------
__device__ __forceinline__ unsigned s2u(const void* p) {
    return (unsigned)__cvta_generic_to_shared(p);
}
__device__ __forceinline__ void cpa16(unsigned dst, const void* src) {
    asm volatile("cp.async.cg.shared.global [%0], [%1], 16;" :: "r"(dst), "l"(src));
}
__device__ __forceinline__ void cp_commit() { asm volatile("cp.async.commit_group;"); }
__device__ __forceinline__ void cp_wait0() { asm volatile("cp.async.wait_group 0;" ::: "memory"); }

__device__ __forceinline__ void ldm4(unsigned* r, unsigned a) {
    asm volatile("ldmatrix.sync.aligned.m8n8.x4.shared.b16 {%0,%1,%2,%3}, [%4];"
                 : "=r"(r[0]), "=r"(r[1]), "=r"(r[2]), "=r"(r[3]) : "r"(a));
}
__device__ __forceinline__ void ldm4t(unsigned* r, unsigned a) {
    asm volatile("ldmatrix.sync.aligned.m8n8.x4.trans.shared.b16 {%0,%1,%2,%3}, [%4];"
                 : "=r"(r[0]), "=r"(r[1]), "=r"(r[2]), "=r"(r[3]) : "r"(a));
}
__device__ __forceinline__ void mma_bf16(float* c, const unsigned* a, unsigned b0, unsigned b1) {
    asm volatile(
        "mma.sync.aligned.m16n8k16.row.col.f32.bf16.bf16.f32 "
        "{%0,%1,%2,%3},{%4,%5,%6,%7},{%8,%9},{%0,%1,%2,%3};"
        : "+f"(c[0]), "+f"(c[1]), "+f"(c[2]), "+f"(c[3])
        : "r"(a[0]), "r"(a[1]), "r"(a[2]), "r"(a[3]), "r"(b0), "r"(b1));
}
__device__ __forceinline__ void split2(float a, float b, bf162& h, bf162& l) {
    h = __floats2bfloat162_rn(a, b);
    float2 hf = __bfloat1622float2(h);
    l = __floats2bfloat162_rn(a - hf.x, b - hf.y);
}
__device__ __forceinline__ float gelu_exact(float x) {
    return 0.5f * x * (1.0f + erff(x * 0.70710678118654752f));
}
__device__ __forceinline__ float brsum(float v, float* sb) {
    int t = threadIdx.x;
    sb[t] = v; __syncthreads();
    for (int s = 128; s > 0; s >>= 1) { if (t < s) sb[t] += sb[t + s]; __syncthreads(); }
    float r = sb[0]; __syncthreads(); return r;
}
__device__ __forceinline__ float brmax(float v, float* sb) {
    int t = threadIdx.x;
    sb[t] = v; __syncthreads();
    for (int s = 128; s > 0; s >>= 1) { if (t < s) sb[t] = fmaxf(sb[t], sb[t + s]); __syncthreads(); }
    float r = sb[0]; __syncthreads(); return r;
}

// conv gemm smem: per buffer Ah[128x40]@0, Al@10240, Bh[32x136]@20480, Bl@29184
#define CBUF 37888
#define CSMEM 75776
// NT smem: Qh@0, Ql@10240, Kh@20480, Kl@30720 (each 128x40 bf16)
#define NBUF 40960
#define NSMEM 81920

// ---------------------------------------------------------------------------
// conv1x1 GEMM (pre-split bf16x3 mma.sync + cp.async, 2 CTA/SM):
// C[b](256 x GN) = A(256 x K) @ B[b](K x GN)
// epi bits: 1 gelu, 2 +R residual, 4 split-out (Ch/Cl), 8 fp32-out (C)
// ---------------------------------------------------------------------------
__global__ __launch_bounds__(256, 2)
void gemm_cp(const bf16* __restrict__ Ah, const bf16* __restrict__ Al, size_t aBs,
             const bf16* __restrict__ Bh, const bf16* __restrict__ Bl, size_t bBs,
             float* __restrict__ C, bf16* __restrict__ Ch, bf16* __restrict__ Cl,
             size_t cBs, const float* __restrict__ R, size_t rBs, int K, int epi) {
    extern __shared__ char smem[];
    int tid = threadIdx.x, wid = tid >> 5, lane = tid & 31;
    int wm = wid & 1, wn = wid >> 1;
    int oBase = blockIdx.y * 128, nBase = blockIdx.x * 128;
    int b = blockIdx.z;
    Ah += (size_t)b * aBs; Al += (size_t)b * aBs;
    Bh += (size_t)b * bBs; Bl += (size_t)b * bBs;
    if (C) C += (size_t)b * cBs;
    if (Ch) { Ch += (size_t)b * cBs; Cl += (size_t)b * cBs; }
    if (R) R += (size_t)b * rBs;

    unsigned sb0 = s2u(smem);

    auto stage = [&](int kk, int buf) {
        unsigned base = sb0 + buf * CBUF;
#pragma unroll
        for (int i = 0; i < 8; i++) {
            int c = tid + 256 * i;
            if (i < 4) {                       // A planes
                int p = c >> 9, r = (c >> 2) & 127, s = c & 3;
                const bf16* src = (p ? Al : Ah) + (size_t)(oBase + r) * K + kk + s * 8;
                cpa16(base + p * 10240 + r * 80 + s * 16, src);
            } else {                           // B planes
                int c2 = c - 1024;
                int p = c2 >> 9, r = (c2 >> 4) & 31, s = c2 & 15;
                const bf16* src = (p ? Bl : Bh) + (size_t)(kk + r) * GN + nBase + s * 8;
                cpa16(base + 20480 + p * 8704 + r * 272 + s * 16, src);
            }
        }
        cp_commit();
    };

    float acc[4][4][4];
#pragma unroll
    for (int i = 0; i < 4; i++)
#pragma unroll
        for (int j = 0; j < 4; j++)
#pragma unroll
            for (int q = 0; q < 4; q++) acc[i][j][q] = 0.0f;

    unsigned aRow = (unsigned)(wm * 64 + (lane & 15));
    unsigned aKof = (unsigned)((lane >> 4) * 8);
    unsigned bKrow = (unsigned)((lane & 7) + ((lane >> 3) & 1) * 8);
    unsigned bNcol = (unsigned)(wn * 32 + ((lane >> 4) & 1) * 8);

    int KT = K >> 5;
    stage(0, 0);
    int cb = 0;
    for (int t = 0; t < KT; t++) {
        cp_wait0();
        __syncthreads();
        if (t + 1 < KT) stage((t + 1) * 32, cb ^ 1);

        const bf16* sA0 = (const bf16*)(smem + cb * CBUF);
        const bf16* sA1 = (const bf16*)(smem + cb * CBUF + 10240);
        const bf16* sB0 = (const bf16*)(smem + cb * CBUF + 20480);
        const bf16* sB1 = (const bf16*)(smem + cb * CBUF + 29184);
#pragma unroll
        for (int ks = 0; ks < 32; ks += 16) {
            unsigned ah[4][4], bh[2][4];
#pragma unroll
            for (int mt = 0; mt < 4; mt++)
                ldm4(ah[mt], s2u(&sA0[(aRow + mt * 16) * 40 + ks + aKof]));
#pragma unroll
            for (int n2 = 0; n2 < 2; n2++)
                ldm4t(bh[n2], s2u(&sB0[(bKrow + ks) * 136 + bNcol + n2 * 16]));
#pragma unroll
            for (int mt = 0; mt < 4; mt++)
#pragma unroll
                for (int nt = 0; nt < 4; nt++)
                    mma_bf16(acc[mt][nt], ah[mt], bh[nt >> 1][(nt & 1) * 2],
                             bh[nt >> 1][(nt & 1) * 2 + 1]);
            unsigned bl[2][4];
#pragma unroll
            for (int n2 = 0; n2 < 2; n2++)
                ldm4t(bl[n2], s2u(&sB1[(bKrow + ks) * 136 + bNcol + n2 * 16]));
#pragma unroll
            for (int mt = 0; mt < 4; mt++)
#pragma unroll
                for (int nt = 0; nt < 4; nt++)
                    mma_bf16(acc[mt][nt], ah[mt], bl[nt >> 1][(nt & 1) * 2],
                             bl[nt >> 1][(nt & 1) * 2 + 1]);
            unsigned al[4][4];
#pragma unroll
            for (int mt = 0; mt < 4; mt++)
                ldm4(al[mt], s2u(&sA1[(aRow + mt * 16) * 40 + ks + aKof]));
#pragma unroll
            for (int mt = 0; mt < 4; mt++)
#pragma unroll
                for (int nt = 0; nt < 4; nt++)
                    mma_bf16(acc[mt][nt], al[mt], bh[nt >> 1][(nt & 1) * 2],
                             bh[nt >> 1][(nt & 1) * 2 + 1]);
        }
        __syncthreads();
        cb ^= 1;
    }

    int g = lane >> 2, tg = lane & 3;
#pragma unroll
    for (int mt = 0; mt < 4; mt++) {
#pragma unroll
        for (int nt = 0; nt < 4; nt++) {
            int r0 = oBase + wm * 64 + mt * 16 + g;
            int col = nBase + wn * 32 + nt * 8 + tg * 2;
            float* c = acc[mt][nt];
#pragma unroll
            for (int h2 = 0; h2 < 2; h2++) {
                size_t base = (size_t)(r0 + h2 * 8) * GN + col;
                float o0 = c[2 * h2], o1 = c[2 * h2 + 1];
                if (epi & 2) {
                    float2 rv = *(const float2*)&R[base];
                    o0 += rv.x; o1 += rv.y;
                }
                if (epi & 1) { o0 = gelu_exact(o0); o1 = gelu_exact(o1); }
                if (epi & 8) *(float2*)&C[base] = make_float2(o0, o1);
                if (epi & 4) {
                    bf162 h, l;
                    split2(o0, o1, h, l);
                    *(bf162*)&Ch[base] = h;
                    *(bf162*)&Cl[base] = l;
                }
            }
        }
    }
}

// ---------------------------------------------------------------------------
// NT score GEMM: P[z][i][j] = sum_{n in chunk} Q[i][n] * K[j][n]
// Both operands K-major bf16 planes. grid (J/128, 2, HB*NSPLIT)
// ---------------------------------------------------------------------------
__global__ __launch_bounds__(256, 2)
void gemmnt_cp(const bf16* __restrict__ Qh, const bf16* __restrict__ Ql, size_t qBs,
               const bf16* __restrict__ Kh, const bf16* __restrict__ Kl, size_t kBs,
               float* __restrict__ P, int J) {
    extern __shared__ char smem[];
    int tid = threadIdx.x, wid = tid >> 5, lane = tid & 31;
    int wm = wid & 1, wn = wid >> 1;
    int z = blockIdx.z, b = z / NSPLIT, s = z % NSPLIT;
    Qh += (size_t)b * qBs; Ql += (size_t)b * qBs;
    Kh += (size_t)b * kBs; Kl += (size_t)b * kBs;
    int iBase = blockIdx.y * 128, jBase = blockIdx.x * 128;
    const int chunk = GN / NSPLIT;    // 1024
    int n0 = s * chunk;
    unsigned sb0 = s2u(smem);

    auto stage = [&](int kk, int buf) {
        unsigned base = sb0 + buf * NBUF;
#pragma unroll
        for (int i = 0; i < 8; i++) {
            int c = tid + 256 * i;
            int p = c >> 9, r = (c >> 2) & 127, sg = c & 3;
            const bf16* pl[4] = { Qh, Ql, Kh, Kl };
            int rowBase = (p < 2) ? iBase : jBase;
            const bf16* src = pl[p] + (size_t)(rowBase + r) * GN + n0 + kk + sg * 8;
            cpa16(base + p * 10240 + r * 80 + sg * 16, src);
        }
        cp_commit();
    };

    float acc[4][4][4];
#pragma unroll
    for (int i = 0; i < 4; i++)
#pragma unroll
        for (int j = 0; j < 4; j++)
#pragma unroll
            for (int q = 0; q < 4; q++) acc[i][j][q] = 0.0f;

    unsigned aRow = (unsigned)(wm * 64 + (lane & 15));
    unsigned aKof = (unsigned)((lane >> 4) * 8);
    unsigned bJrow = (unsigned)(wn * 32 + (lane & 7) + ((lane >> 4) & 1) * 8);
    unsigned bKof = (unsigned)(((lane >> 3) & 1) * 8);

    int KT = chunk >> 5;              // 32
    stage(0, 0);
    int cb = 0;
    for (int t = 0; t < KT; t++) {
        cp_wait0();
        __syncthreads();
        if (t + 1 < KT) stage((t + 1) * 32, cb ^ 1);

        const bf16* sQ0 = (const bf16*)(smem + cb * NBUF);
        const bf16* sQ1 = (const bf16*)(smem + cb * NBUF + 10240);
        const bf16* sK0 = (const bf16*)(smem + cb * NBUF + 20480);
        const bf16* sK1 = (const bf16*)(smem + cb * NBUF + 30720);
#pragma unroll
        for (int ks = 0; ks < 32; ks += 16) {
            unsigned ah[4][4], bh[2][4];
#pragma unroll
            for (int mt = 0; mt < 4; mt++)
                ldm4(ah[mt], s2u(&sQ0[(aRow + mt * 16) * 40 + ks + aKof]));
#pragma unroll
            for (int n2 = 0; n2 < 2; n2++)
                ldm4(bh[n2], s2u(&sK0[(bJrow + n2 * 16) * 40 + ks + bKof]));
#pragma unroll
            for (int mt = 0; mt < 4; mt++)
#pragma unroll
                for (int nt = 0; nt < 4; nt++)
                    mma_bf16(acc[mt][nt], ah[mt], bh[nt >> 1][(nt & 1) * 2],
                             bh[nt >> 1][(nt & 1) * 2 + 1]);
            unsigned bl[2][4];
#pragma unroll
            for (int n2 = 0; n2 < 2; n2++)
                ldm4(bl[n2], s2u(&sK1[(bJrow + n2 * 16) * 40 + ks + bKof]));
#pragma unroll
            for (int mt = 0; mt < 4; mt++)
#pragma unroll
                for (int nt = 0; nt < 4; nt++)
                    mma_bf16(acc[mt][nt], ah[mt], bl[nt >> 1][(nt & 1) * 2],
                             bl[nt >> 1][(nt & 1) * 2 + 1]);
            unsigned al[4][4];
#pragma unroll
            for (int mt = 0; mt < 4; mt++)
                ldm4(al[mt], s2u(&sQ1[(aRow + mt * 16) * 40 + ks + aKof]));
#pragma unroll
            for (int mt = 0; mt < 4; mt++)
#pragma unroll
                for (int nt = 0; nt < 4; nt++)
                    mma_bf16(acc[mt][nt], al[mt], bh[nt >> 1][(nt & 1) * 2],
                             bh[nt >> 1][(nt & 1) * 2 + 1]);
        }
        __syncthreads();
        cb ^= 1;
    }

    int g = lane >> 2, tg = lane & 3;
#pragma unroll
    for (int mt = 0; mt < 4; mt++) {
#pragma unroll
        for (int nt = 0; nt < 4; nt++) {
            int r0 = iBase + wm * 64 + mt * 16 + g;
            int col = jBase + wn * 32 + nt * 8 + tg * 2;
            float* c = acc[mt][nt];
#pragma unroll
            for (int h2 = 0; h2 < 2; h2++) {
                size_t base = ((size_t)z * 256 + r0 + h2 * 8) * J + col;
                *(float2*)&P[base] = make_float2(c[2 * h2], c[2 * h2 + 1]);
            }
        }
    }
}

// ---------------------------------------------------------------------------
// split fp32 array -> bf16 hi/lo planes
// ---------------------------------------------------------------------------
__global__ __launch_bounds__(256)
void split_arr(const float* __restrict__ X, bf16* __restrict__ H,
               bf16* __restrict__ L, int n4) {
    int i = blockIdx.x * 256 + threadIdx.x;
    if (i < n4) {
        float4 v = ((const float4*)X)[i];
        bf162 h0, l0, h1, l1;
        split2(v.x, v.y, h0, l0);
        split2(v.z, v.w, h1, l1);
        ((bf162*)H)[2 * i] = h0; ((bf162*)H)[2 * i + 1] = h1;
        ((bf162*)L)[2 * i] = l0; ((bf162*)L)[2 * i + 1] = l1;
    }
}

// ---------------------------------------------------------------------------
// instance norm (affine) -> split bf16 planes. one block per row.
// ---------------------------------------------------------------------------
__global__ __launch_bounds__(256)
void inorm_split(const float* __restrict__ X, bf16* __restrict__ H, bf16* __restrict__ L,
                 const float* __restrict__ gamma, const float* __restrict__ beta) {
    __shared__ float sb[256];
    int row = blockIdx.x, cch = row & (ECH - 1);
    const float4* xr = (const float4*)(X + (size_t)row * GN);
    bf162* hr = (bf162*)(H + (size_t)row * GN);
    bf162* lr = (bf162*)(L + (size_t)row * GN);
    float s = 0.f, ss = 0.f;
    for (int i = threadIdx.x; i < GN / 4; i += 256) {
        float4 v = xr[i];
        s += v.x + v.y + v.z + v.w;
        ss += v.x * v.x + v.y * v.y + v.z * v.z + v.w * v.w;
    }
    float tot = brsum(s, sb), tot2 = brsum(ss, sb);
    const float inv = 1.0f / (float)GN;
    float mu = tot * inv, var = tot2 * inv - mu * mu;
    float rstd = rsqrtf(var + 1e-5f);
    float a = rstd * gamma[cch], bb = beta[cch] - mu * a;
    for (int i = threadIdx.x; i < GN / 4; i += 256) {
        float4 v = xr[i];
        float y0 = v.x * a + bb, y1 = v.y * a + bb;
        float y2 = v.z * a + bb, y3 = v.w * a + bb;
        bf162 h0, l0, h1, l1;
        split2(y0, y1, h0, l0);
        split2(y2, y3, h1, l1);
        hr[2 * i] = h0; hr[2 * i + 1] = h1;
        lr[2 * i] = l0; lr[2 * i + 1] = l1;
    }
}

// ---------------------------------------------------------------------------
// reduce NSPLIT partials -> scale -> inorm -> softmax -> split bf16 out
// ---------------------------------------------------------------------------
__global__ __launch_bounds__(256)
void softmax_split(const float* __restrict__ P, bf16* __restrict__ SH,
                   bf16* __restrict__ SL, int J, float scale) {
    __shared__ float rowbuf[512];
    __shared__ float sb[256];
    int row = blockIdx.x, b = row >> 8, i = row & 255, tid = threadIdx.x;
    for (int j = tid; j < J; j += 256) {
        float v = 0.f;
#pragma unroll
        for (int s = 0; s < NSPLIT; s++)
            v += P[(((size_t)(b * NSPLIT + s) * 256) + i) * J + j];
        rowbuf[j] = v * scale;
    }
    __syncthreads();
    float ls = 0.f;
    for (int j = tid; j < J; j += 256) ls += rowbuf[j];
    float mean = brsum(ls, sb) / (float)J;
    float lv = 0.f;
    for (int j = tid; j < J; j += 256) { float d = rowbuf[j] - mean; lv += d * d; }
    float rstd = rsqrtf(brsum(lv, sb) / (float)J + 1e-5f);
    float lm = -1e30f;
    for (int j = tid; j < J; j += 256) {
        float tt = (rowbuf[j] - mean) * rstd;
        rowbuf[j] = tt;
        lm = fmaxf(lm, tt);
    }
    float mx = brmax(lm, sb);
    float le = 0.f;
    for (int j = tid; j < J; j += 256) {
        float e = expf(rowbuf[j] - mx);
        rowbuf[j] = e;
        le += e;
    }
    float rden = 1.0f / brsum(le, sb);
    size_t ob = ((size_t)b * 256 + i) * J;
    for (int j = tid; j < J; j += 256) {
        float y = rowbuf[j] * rden;
        bf16 h = __float2bfloat16_rn(y);
        SH[ob + j] = h;
        SL[ob + j] = __float2bfloat16_rn(y - __bfloat162float(h));
    }
}

// ---------------------------------------------------------------------------
// launch
// ---------------------------------------------------------------------------
extern "C" void kernel_launch(void* const* d_in, const int* in_sizes, int n_in,
                              void* d_out, int out_size) {
    const float* feat  = (const float*)d_in[0];
    const float* kv    = (const float*)d_in[1];
    const float* wsrc[8] = { (const float*)d_in[2], (const float*)d_in[3],
                             (const float*)d_in[4], (const float*)d_in[5],
                             (const float*)d_in[6], (const float*)d_in[7],
                             (const float*)d_in[8], (const float*)d_in[9] };
    // slots: 0 w_in, 1 w_out, 2 wq_sa, 3 wk_sa, 4 wv_sa, 5 wo_sa, 6 wq_ca, 7 wo_ca
    const float* ag = (const float*)d_in[10];
    const float* ab = (const float*)d_in[11];
    const float* eg = (const float*)d_in[12];
    const float* eb = (const float*)d_in[13];
    float* out = (float*)d_out;

    float *emb, *pre, *pu, *plw;
    bf16 *fh, *fl, *nh, *nl, *qh, *ql, *kh, *kl, *vh, *vl, *th, *tl;
    bf16 *kvh, *kvl, *suh, *sul, *slh, *sll, *wh, *wl;
    cudaGetSymbolAddress((void**)&emb, g_emb);
    cudaGetSymbolAddress((void**)&pre, g_pre);
    cudaGetSymbolAddress((void**)&pu, g_pu);
    cudaGetSymbolAddress((void**)&plw, g_plw);
    cudaGetSymbolAddress((void**)&fh, g_fh);  cudaGetSymbolAddress((void**)&fl, g_fl);
    cudaGetSymbolAddress((void**)&nh, g_nh);  cudaGetSymbolAddress((void**)&nl, g_nl);
    cudaGetSymbolAddress((void**)&qh, g_qh);  cudaGetSymbolAddress((void**)&ql, g_ql);
    cudaGetSymbolAddress((void**)&kh, g_kh);  cudaGetSymbolAddress((void**)&kl, g_kl);
    cudaGetSymbolAddress((void**)&vh, g_vh);  cudaGetSymbolAddress((void**)&vl, g_vl);
    cudaGetSymbolAddress((void**)&th, g_th);  cudaGetSymbolAddress((void**)&tl, g_tl);
    cudaGetSymbolAddress((void**)&kvh, g_kvh); cudaGetSymbolAddress((void**)&kvl, g_kvl);
    cudaGetSymbolAddress((void**)&suh, g_suh); cudaGetSymbolAddress((void**)&sul, g_sul);
    cudaGetSymbolAddress((void**)&slh, g_slh); cudaGetSymbolAddress((void**)&sll, g_sll);
    cudaGetSymbolAddress((void**)&wh, g_wh);  cudaGetSymbolAddress((void**)&wl, g_wl);

    cudaFuncSetAttribute(gemm_cp, cudaFuncAttributeMaxDynamicSharedMemorySize, CSMEM);
    cudaFuncSetAttribute(gemmnt_cp, cudaFuncAttributeMaxDynamicSharedMemorySize, NSMEM);

    const float scale = 1.0f / 128.0f;
    dim3 blk(256);
    dim3 g8(GN / 128, 2, 8);
    dim3 g4(GN / 128, 2, 4);

    // pre-split inputs
    for (int w = 0; w < 8; w++)
        split_arr<<<64, blk>>>(wsrc[w], wh + w * 65536, wl + w * 65536, 16384);
    split_arr<<<32768, blk>>>(feat, fh, fl, 8388608);
    split_arr<<<8192, blk>>>(kv, kvh, kvl, 2097152);

    // 1. emb = gelu(w_in @ feat)  (fp32)
    gemm_cp<<<g8, blk, CSMEM>>>(wh, wl, 0, fh, fl, BSTR, emb, nullptr, nullptr,
                                BSTR, nullptr, 0, 256, 1 | 8);
    // 2. nrm = inorm(emb) -> split planes
    inorm_split<<<NB * ECH, blk>>>(emb, nh, nl, ag, ab);
    // 3-5. upper Q/K/V (split-only outputs)
    gemm_cp<<<g4, blk, CSMEM>>>(wh + 2 * 65536, wl + 2 * 65536, 0, nh + TOT4, nl + TOT4,
                                BSTR, nullptr, qh, ql, BSTR, nullptr, 0, 256, 4);
    gemm_cp<<<g4, blk, CSMEM>>>(wh + 3 * 65536, wl + 3 * 65536, 0, nh + TOT4, nl + TOT4,
                                BSTR, nullptr, kh, kl, BSTR, nullptr, 0, 256, 4);
    gemm_cp<<<g4, blk, CSMEM>>>(wh + 4 * 65536, wl + 4 * 65536, 0, nh + TOT4, nl + TOT4,
                                BSTR, nullptr, vh, vl, BSTR, nullptr, 0, 256, 4);
    // 6. upper score partials
    gemmnt_cp<<<dim3(2, 2, HB * NSPLIT), blk, NSMEM>>>(qh, ql, BSTR, kh, kl, BSTR, pu, 256);
    // 7. softmax -> split
    softmax_split<<<HB * 256, blk>>>(pu, suh, sul, 256, scale);
    // 8. t = su @ v (split out)
    gemm_cp<<<g4, blk, CSMEM>>>(suh, sul, 65536, vh, vl, BSTR, nullptr, th, tl,
                                BSTR, nullptr, 0, 256, 4);
    // 9. pre_u = wo_sa @ t + emb_u (fp32)
    gemm_cp<<<g4, blk, CSMEM>>>(wh + 5 * 65536, wl + 5 * 65536, 0, th, tl, BSTR,
                                pre + TOT4, nullptr, nullptr, BSTR, emb + TOT4, BSTR, 256, 2 | 8);
    // 10. lower Ql (reuse q planes)
    gemm_cp<<<g4, blk, CSMEM>>>(wh + 6 * 65536, wl + 6 * 65536, 0, nh, nl, BSTR,
                                nullptr, qh, ql, BSTR, nullptr, 0, 256, 4);
    // 11. lower score partials (kv shared: kBs = 0)
    gemmnt_cp<<<dim3(4, 2, HB * NSPLIT), blk, NSMEM>>>(qh, ql, BSTR, kvh, kvl, 0, plw, 512);
    // 12. softmax (J=512)
    softmax_split<<<HB * 256, blk>>>(plw, slh, sll, 512, scale);
    // 13. ca = sl @ kv (K=512, split out)
    gemm_cp<<<g4, blk, CSMEM>>>(slh, sll, 131072, kvh, kvl, 0, nullptr, th, tl,
                                BSTR, nullptr, 0, 512, 4);
    // 14. pre_l = wo_ca @ ca + emb_l (fp32)
    gemm_cp<<<g4, blk, CSMEM>>>(wh + 7 * 65536, wl + 7 * 65536, 0, th, tl, BSTR,
                                pre, nullptr, nullptr, BSTR, emb, BSTR, 256, 2 | 8);
    // 15. nrm2 = inorm(pre) -> split
    inorm_split<<<NB * ECH, blk>>>(pre, nh, nl, eg, eb);
    // 16. out = gelu(w_out @ nrm2) (fp32)
    gemm_cp<<<g8, blk, CSMEM>>>(wh + 65536, wl + 65536, 0, nh, nl, BSTR, out,
                                nullptr, nullptr, BSTR, nullptr, 0, 256, 1 | 8);
}